// round 12
// baseline (speedup 1.0000x reference)
#include <cuda_runtime.h>
#include <cuda_bf16.h>
#include <cstdint>
#include <math.h>

#define BATCH 4
#define DMODEL 1024
#define SEQ 2048
#define NHEAD 16
#define HDIM 64
#define NTOK (BATCH * SEQ)   // 8192

// ===================== device scratch (no allocation) =====================
__device__ float g_freq[DMODEL / 2];
__device__ __align__(16) __nv_bfloat16 g_xhi[(size_t)NTOK * DMODEL];  // x+PE hi; later attn-out hi
__device__ __align__(16) __nv_bfloat16 g_xlo[(size_t)NTOK * DMODEL];  // x+PE lo; later attn-out lo
__device__ __align__(16) __nv_bfloat16 g_whi[4][(size_t)DMODEL * DMODEL];
__device__ __align__(16) __nv_bfloat16 g_wlo[4][(size_t)DMODEL * DMODEL];
// bf16 hi/lo Q,K ([bh][s][hd], Q pre-scaled by 0.125) and V transposed ([bh][hd][s])
__device__ __align__(16) __nv_bfloat16 g_qhi[(size_t)NTOK * DMODEL];
__device__ __align__(16) __nv_bfloat16 g_qlo[(size_t)NTOK * DMODEL];
__device__ __align__(16) __nv_bfloat16 g_khi[(size_t)NTOK * DMODEL];
__device__ __align__(16) __nv_bfloat16 g_klo[(size_t)NTOK * DMODEL];
__device__ __align__(16) __nv_bfloat16 g_vthi[(size_t)NTOK * DMODEL];
__device__ __align__(16) __nv_bfloat16 g_vtlo[(size_t)NTOK * DMODEL];

// ===================== PTX helpers (family-agnostic) =====================
__device__ __forceinline__ uint32_t smem_u32(const void* p) {
    uint32_t a;
    asm("{ .reg .u64 t; cvta.to.shared.u64 t, %1; cvt.u32.u64 %0, t; }" : "=r"(a) : "l"(p));
    return a;
}
__device__ __forceinline__ void ldmx4(uint32_t* r, uint32_t addr) {
    asm volatile("ldmatrix.sync.aligned.m8n8.x4.shared.b16 {%0,%1,%2,%3}, [%4];"
                 : "=r"(r[0]), "=r"(r[1]), "=r"(r[2]), "=r"(r[3]) : "r"(addr));
}
__device__ __forceinline__ void mma16816(float* d, const uint32_t* a, const uint32_t* b) {
    asm volatile("mma.sync.aligned.m16n8k16.row.col.f32.bf16.bf16.f32 "
                 "{%0,%1,%2,%3}, {%4,%5,%6,%7}, {%8,%9}, {%0,%1,%2,%3};"
                 : "+f"(d[0]), "+f"(d[1]), "+f"(d[2]), "+f"(d[3])
                 : "r"(a[0]), "r"(a[1]), "r"(a[2]), "r"(a[3]), "r"(b[0]), "r"(b[1]));
}
__device__ __forceinline__ void cpa16(uint32_t saddr, const void* g) {
    asm volatile("cp.async.cg.shared.global [%0], [%1], 16;" :: "r"(saddr), "l"(g));
}
#define CP_COMMIT asm volatile("cp.async.commit_group;" ::: "memory")
#define CP_WAIT1 asm volatile("cp.async.wait_group 1;" ::: "memory")
#define CP_WAIT0 asm volatile("cp.async.wait_group 0;" ::: "memory")

// split fp32 pair into packed bf16x2 hi and lo (low half = first arg)
__device__ __forceinline__ void split2(float x0, float x1, uint32_t& hi, uint32_t& lo) {
    __nv_bfloat162 h = __floats2bfloat162_rn(x0, x1);
    hi = *(uint32_t*)&h;
    float r0 = x0 - __bfloat162float(h.x);
    float r1 = x1 - __bfloat162float(h.y);
    __nv_bfloat162 l = __floats2bfloat162_rn(r0, r1);
    lo = *(uint32_t*)&l;
}

// ===================== prep kernels =====================
__global__ void k_init_freq() {
    int i = threadIdx.x;
    if (i < DMODEL / 2)
        g_freq[i] = (float)exp(-(double)(2 * i) * (9.210340371976184 / 1024.0));
}

// x + PE, transpose [B,D,S] -> [B,S,D], write bf16 hi/lo split
__global__ void k_pe_split(const float* __restrict__ x) {
    __shared__ float tile[32][33];
    int b = blockIdx.z, d0 = blockIdx.y * 32, s0 = blockIdx.x * 32;
    int txx = threadIdx.x, tyy = threadIdx.y;
    const float* xb = x + (size_t)b * DMODEL * SEQ;
#pragma unroll
    for (int r = 0; r < 4; r++) {
        int d = d0 + tyy + r * 8, s = s0 + txx;
        float ang = (float)s * g_freq[d >> 1];
        float pe = (d & 1) ? cosf(ang) : sinf(ang);
        tile[tyy + r * 8][txx] = xb[(size_t)d * SEQ + s] + pe;
    }
    __syncthreads();
#pragma unroll
    for (int r = 0; r < 4; r++) {
        int sl = tyy + r * 8;
        float v = tile[txx][sl];
        __nv_bfloat16 hi = __float2bfloat16(v);
        float lo = v - __bfloat162float(hi);
        size_t idx = ((size_t)b * SEQ + s0 + sl) * DMODEL + d0 + txx;
        g_xhi[idx] = hi;
        g_xlo[idx] = __float2bfloat16(lo);
    }
}

// Split all four weight matrices into bf16 hi/lo (one launch)
__global__ void k_split_w4(const float* __restrict__ w0, const float* __restrict__ w1,
                           const float* __restrict__ w2, const float* __restrict__ w3) {
    int wsel = blockIdx.x >> 10;
    const float* w = (wsel == 0) ? w0 : (wsel == 1) ? w1 : (wsel == 2) ? w2 : w3;
    int i = ((blockIdx.x & 1023) * 256 + threadIdx.x) * 4;
    float4 v = *(const float4*)(w + i);
    __nv_bfloat16* hi = g_whi[wsel];
    __nv_bfloat16* lo = g_wlo[wsel];
    float a[4] = {v.x, v.y, v.z, v.w};
#pragma unroll
    for (int j = 0; j < 4; j++) {
        __nv_bfloat16 h = __float2bfloat16(a[j]);
        hi[i + j] = h;
        lo[i + j] = __float2bfloat16(a[j] - __bfloat162float(h));
    }
}

// ===================== HMMA GEMM: C[8192,1024] = A * W^T + bias ==============
// Composite chunks: {Ahi, Alo, Whi, Wlo} x 64-K slice per chunk (64KB), 16 chunks.
// 3-term split: Ahi*Whi + Ahi*Wlo + Alo*Whi; fp32 register accumulators.
// 3-stage cp.async pipeline (192KB smem), ONE __syncthreads per chunk.
// 512 threads, 16 warps as 4(M) x 4(N): warp tile 32x32, 2x4 m16n8 fragments.
#define MM_STG 65536u
#define MM_SMEM (3 * 65536)

__global__ __launch_bounds__(512) void k_mm(int wsel,
                                            const float* __restrict__ bias,
                                            float* __restrict__ outp,
                                            int which) {
    extern __shared__ char smem[];
    uint32_t sb = smem_u32(smem);
    int tid = threadIdx.x;
    int warp = tid >> 5, lane = tid & 31;
    int wm = warp & 3, wn = warp >> 2;
    int n0 = blockIdx.x * 128, m0 = blockIdx.y * 128;

    const __nv_bfloat16* WH = g_whi[wsel];
    const __nv_bfloat16* WL = g_wlo[wsel];

    float acc[2][4][4];
#pragma unroll
    for (int mt = 0; mt < 2; mt++)
#pragma unroll
        for (int nt = 0; nt < 4; nt++)
#pragma unroll
            for (int e = 0; e < 4; e++) acc[mt][nt][e] = 0.0f;

    // staging: thread -> (row = it*64 + tid>>3, col16B = tid&7), SW128 swizzle
    int ldr = tid >> 3, ldc = tid & 7;

#define MM_ISSUE(kcv, st) do {                                                      \
        uint32_t bs = sb + (uint32_t)(st) * MM_STG;                                 \
        int _kc = (kcv);                                                            \
        _Pragma("unroll") for (int it = 0; it < 2; it++) {                          \
            int row = it * 64 + ldr;                                                \
            uint32_t off = (uint32_t)(row * 128 + ldc * 16);                        \
            off ^= (off >> 3) & 0x70;                                               \
            size_t ga = (size_t)(m0 + row) * DMODEL + _kc * 64 + ldc * 8;           \
            size_t gb = (size_t)(n0 + row) * DMODEL + _kc * 64 + ldc * 8;           \
            cpa16(bs + off,          g_xhi + ga);                                   \
            cpa16(bs + 16384 + off,  g_xlo + ga);                                   \
            cpa16(bs + 32768 + off,  WH + gb);                                      \
            cpa16(bs + 49152 + off,  WL + gb);                                      \
        }                                                                           \
        CP_COMMIT;                                                                  \
    } while (0)

    // per-thread ldmatrix row/byte components (canonical m16n8k16 fragments)
    int a_row = wm * 32 + (lane & 15);                         // + mt*16
    int a_kb = (lane >> 4) * 16;                               // + k16*32
    int b_row = wn * 32 + (lane & 7) + ((lane >> 4) & 1) * 8;  // + ntp*16
    int b_kb = ((lane >> 3) & 1) * 16;

    MM_ISSUE(0, 0);
    MM_ISSUE(1, 1);

#pragma unroll 1
    for (int kc = 0; kc < 16; kc++) {
        int st = kc % 3;
        if (kc + 1 < 16) CP_WAIT1; else CP_WAIT0;   // this thread's chunk kc arrived
        __syncthreads();                             // visible to all; stage (kc-1)%3 free
        if (kc + 2 < 16) MM_ISSUE(kc + 2, (kc + 2) % 3);
        uint32_t AH = sb + (uint32_t)st * MM_STG;
        uint32_t AL = AH + 16384u, BH = AH + 32768u, BL = AH + 49152u;
#pragma unroll
        for (int k16 = 0; k16 < 4; k16++) {
            int kbyte = k16 * 32;
            uint32_t ah[2][4], al[2][4], bh[2][4], bl[2][4];
#pragma unroll
            for (int mt = 0; mt < 2; mt++) {
                uint32_t off = (uint32_t)((a_row + mt * 16) * 128 + kbyte + a_kb);
                off ^= (off >> 3) & 0x70;
                ldmx4(ah[mt], AH + off);
                ldmx4(al[mt], AL + off);
            }
#pragma unroll
            for (int p = 0; p < 2; p++) {
                uint32_t off = (uint32_t)((b_row + p * 16) * 128 + kbyte + b_kb);
                off ^= (off >> 3) & 0x70;
                ldmx4(bh[p], BH + off);
                ldmx4(bl[p], BL + off);
            }
#pragma unroll
            for (int mt = 0; mt < 2; mt++)
#pragma unroll
                for (int nt = 0; nt < 4; nt++) {
                    mma16816(acc[mt][nt], ah[mt], &bh[nt >> 1][(nt & 1) * 2]);
                    mma16816(acc[mt][nt], ah[mt], &bl[nt >> 1][(nt & 1) * 2]);
                    mma16816(acc[mt][nt], al[mt], &bh[nt >> 1][(nt & 1) * 2]);
                }
        }
    }

    // ---- epilogue: d0,d1 -> (r0, c0..c0+1); d2,d3 -> (r0+8, ..)
    int r0 = lane >> 2, c0 = (lane & 3) * 2;
    int mbase = m0 + wm * 32, nbase = n0 + wn * 32;
    if (which <= 1) {
        // Q (scaled 0.125) or K -> bf16 hi/lo in [bh][s][hd]
        __nv_bfloat16* HI = which ? g_khi : g_qhi;
        __nv_bfloat16* LO = which ? g_klo : g_qlo;
        float scale = which ? 1.0f : 0.125f;
#pragma unroll
        for (int mt = 0; mt < 2; mt++)
#pragma unroll
            for (int half = 0; half < 2; half++) {
                int row = mbase + mt * 16 + r0 + half * 8;
                int bb2 = row >> 11;
                int sq = row & (SEQ - 1);
#pragma unroll
                for (int nt = 0; nt < 4; nt++) {
                    int jg = nbase + nt * 8 + c0;
                    int h = jg >> 6, hd = jg & 63;
                    float v0 = (acc[mt][nt][half * 2 + 0] + bias[jg + 0]) * scale;
                    float v1 = (acc[mt][nt][half * 2 + 1] + bias[jg + 1]) * scale;
                    uint32_t hi, lo;
                    split2(v0, v1, hi, lo);
                    size_t idx = ((size_t)(bb2 * NHEAD + h) * SEQ + sq) * HDIM + hd;
                    *(uint32_t*)&HI[idx] = hi;
                    *(uint32_t*)&LO[idx] = lo;
                }
            }
    } else if (which == 2) {
        // V -> bf16 hi/lo transposed [bh][hd][s]
#pragma unroll
        for (int mt = 0; mt < 2; mt++)
#pragma unroll
            for (int half = 0; half < 2; half++) {
                int row = mbase + mt * 16 + r0 + half * 8;
                int bb2 = row >> 11;
                int sq = row & (SEQ - 1);
#pragma unroll
                for (int nt = 0; nt < 4; nt++) {
                    int jg = nbase + nt * 8 + c0;
                    int h = jg >> 6, hd = jg & 63;
                    float v0 = acc[mt][nt][half * 2 + 0] + bias[jg + 0];
                    float v1 = acc[mt][nt][half * 2 + 1] + bias[jg + 1];
                    __nv_bfloat16 h0 = __float2bfloat16(v0);
                    __nv_bfloat16 h1 = __float2bfloat16(v1);
                    __nv_bfloat16 l0 = __float2bfloat16(v0 - __bfloat162float(h0));
                    __nv_bfloat16 l1 = __float2bfloat16(v1 - __bfloat162float(h1));
                    size_t tb = ((size_t)(bb2 * NHEAD + h) * HDIM + hd) * SEQ + sq;
                    g_vthi[tb] = h0; g_vtlo[tb] = l0;
                    g_vthi[tb + SEQ] = h1; g_vtlo[tb + SEQ] = l1;
                }
            }
    } else {
        // final projection: out[B, D, S]
#pragma unroll
        for (int mt = 0; mt < 2; mt++)
#pragma unroll
            for (int half = 0; half < 2; half++) {
                int row = mbase + mt * 16 + r0 + half * 8;
                int bb2 = row >> 11;
                int sq = row & (SEQ - 1);
#pragma unroll
                for (int nt = 0; nt < 4; nt++) {
                    int jg = nbase + nt * 8 + c0;
                    outp[((size_t)bb2 * DMODEL + jg) * SEQ + sq] =
                        acc[mt][nt][half * 2 + 0] + bias[jg];
                    outp[((size_t)bb2 * DMODEL + jg + 1) * SEQ + sq] =
                        acc[mt][nt][half * 2 + 1] + bias[jg + 1];
                }
            }
    }
}

// ===================== tensor-core flash attention =====================
// Br=128 (8 warps x m16), Bc=64. S = QhiKhi + QloKhi + QhiKlo (fp32 frags),
// softmax in fragments, P converted to bf16 hi/lo in registers (C->A layout match),
// O += PhiVhi + PloVhi + PhiVlo. K/V tiles cp.async double-buffered.
// smem: stage s at s*32768: KH 8K | KL 8K | VH 8K | VL 8K. Q staged at 0 in prologue.
#define FL2_SMEM 65536
__global__ __launch_bounds__(256) void k_flash2() {
    extern __shared__ char sm2[];
    uint32_t sb = smem_u32(sm2);
    int tid = threadIdx.x;
    int warp = tid >> 5, lane = tid & 31;
    int bh = blockIdx.y;
    int q0 = blockIdx.x * 128;

    const __nv_bfloat16* qh_g = g_qhi + ((size_t)bh * SEQ + q0) * HDIM;
    const __nv_bfloat16* ql_g = g_qlo + ((size_t)bh * SEQ + q0) * HDIM;
    const __nv_bfloat16* kh_g = g_khi + (size_t)bh * SEQ * HDIM;
    const __nv_bfloat16* kl_g = g_klo + (size_t)bh * SEQ * HDIM;
    const __nv_bfloat16* vh_g = g_vthi + (size_t)bh * HDIM * SEQ;
    const __nv_bfloat16* vl_g = g_vtlo + (size_t)bh * HDIM * SEQ;

    // ---- stage Q (hi @0, lo @16384), extract fragments, then free the space
#pragma unroll
    for (int it = 0; it < 4; it++) {
        int c = it * 256 + tid;
        int r = c >> 3, col = c & 7;
        uint32_t off = (uint32_t)(r * 128 + col * 16);
        off ^= (off >> 3) & 0x70;
        *(uint4*)(sm2 + off) = *(const uint4*)(qh_g + (size_t)r * HDIM + col * 8);
        *(uint4*)(sm2 + 16384 + off) = *(const uint4*)(ql_g + (size_t)r * HDIM + col * 8);
    }
    __syncthreads();
    uint32_t qh[4][4], ql[4][4];
    {
        int a_row = warp * 16 + (lane & 15);
        int a_kb = (lane >> 4) * 16;
#pragma unroll
        for (int t = 0; t < 4; t++) {
            uint32_t off = (uint32_t)(a_row * 128 + t * 32 + a_kb);
            off ^= (off >> 3) & 0x70;
            ldmx4(qh[t], sb + off);
            ldmx4(ql[t], sb + 16384 + off);
        }
    }
    __syncthreads();

    int b_row = (lane & 7) + ((lane >> 4) & 1) * 8;   // + pair*16
    int b_kb = ((lane >> 3) & 1) * 16;                // + t*32

#define FL_LOAD(s, kt) do {                                                     \
        uint32_t bs = sb + (uint32_t)(s) * 32768u;                              \
        int kb0 = (kt) * 64;                                                    \
        _Pragma("unroll") for (int it = 0; it < 2; it++) {                      \
            int c = it * 256 + tid;                                             \
            int r = c >> 3, col = c & 7;                                        \
            uint32_t off = (uint32_t)(r * 128 + col * 16);                      \
            off ^= (off >> 3) & 0x70;                                           \
            cpa16(bs + off, kh_g + (size_t)(kb0 + r) * HDIM + col * 8);         \
            cpa16(bs + 8192 + off, kl_g + (size_t)(kb0 + r) * HDIM + col * 8);  \
            cpa16(bs + 16384 + off, vh_g + (size_t)r * SEQ + kb0 + col * 8);    \
            cpa16(bs + 24576 + off, vl_g + (size_t)r * SEQ + kb0 + col * 8);    \
        }                                                                       \
    } while (0)

    float oa[8][4];
#pragma unroll
    for (int j = 0; j < 8; j++)
#pragma unroll
        for (int e = 0; e < 4; e++) oa[j][e] = 0.0f;
    float m0 = -1e30f, m1 = -1e30f, l0 = 0.0f, l1 = 0.0f;

    FL_LOAD(0, 0);
    CP_COMMIT;

#pragma unroll 1
    for (int kt = 0; kt < SEQ / 64; kt++) {
        int s = kt & 1;
        if (kt + 1 < SEQ / 64) {
            FL_LOAD(s ^ 1, kt + 1);
            CP_COMMIT;
            CP_WAIT1;
        } else {
            CP_WAIT0;
        }
        __syncthreads();
        uint32_t kh_s = sb + (uint32_t)s * 32768u;
        uint32_t kl_s = kh_s + 8192u, vh_s = kh_s + 16384u, vl_s = kh_s + 24576u;

        // ---- S = Q K^T (3-term)
        float sv[8][4];
#pragma unroll
        for (int j = 0; j < 8; j++)
#pragma unroll
            for (int e = 0; e < 4; e++) sv[j][e] = 0.0f;
#pragma unroll
        for (int t = 0; t < 4; t++) {
            uint32_t bf_[4][4];
            uint32_t offs[4];
#pragma unroll
            for (int p = 0; p < 4; p++) {
                uint32_t off = (uint32_t)((p * 16 + b_row) * 128 + t * 32 + b_kb);
                off ^= (off >> 3) & 0x70;
                offs[p] = off;
                ldmx4(bf_[p], kh_s + off);
            }
#pragma unroll
            for (int j = 0; j < 8; j++) mma16816(sv[j], qh[t], &bf_[j >> 1][(j & 1) * 2]);
#pragma unroll
            for (int j = 0; j < 8; j++) mma16816(sv[j], ql[t], &bf_[j >> 1][(j & 1) * 2]);
#pragma unroll
            for (int p = 0; p < 4; p++) ldmx4(bf_[p], kl_s + offs[p]);
#pragma unroll
            for (int j = 0; j < 8; j++) mma16816(sv[j], qh[t], &bf_[j >> 1][(j & 1) * 2]);
        }

        // ---- online softmax (rows r0 = d0,d1; r0+8 = d2,d3; reduce over quad)
        float mx0 = sv[0][0], mx1 = sv[0][2];
#pragma unroll
        for (int j = 0; j < 8; j++) {
            mx0 = fmaxf(mx0, fmaxf(sv[j][0], sv[j][1]));
            mx1 = fmaxf(mx1, fmaxf(sv[j][2], sv[j][3]));
        }
        mx0 = fmaxf(mx0, __shfl_xor_sync(0xffffffffu, mx0, 1));
        mx0 = fmaxf(mx0, __shfl_xor_sync(0xffffffffu, mx0, 2));
        mx1 = fmaxf(mx1, __shfl_xor_sync(0xffffffffu, mx1, 1));
        mx1 = fmaxf(mx1, __shfl_xor_sync(0xffffffffu, mx1, 2));
        float mn0 = fmaxf(m0, mx0), mn1 = fmaxf(m1, mx1);
        float al0 = __expf(m0 - mn0), al1 = __expf(m1 - mn1);
        m0 = mn0; m1 = mn1;
        float s0 = 0.0f, s1 = 0.0f;
#pragma unroll
        for (int j = 0; j < 8; j++) {
            sv[j][0] = __expf(sv[j][0] - mn0); s0 += sv[j][0];
            sv[j][1] = __expf(sv[j][1] - mn0); s0 += sv[j][1];
            sv[j][2] = __expf(sv[j][2] - mn1); s1 += sv[j][2];
            sv[j][3] = __expf(sv[j][3] - mn1); s1 += sv[j][3];
        }
        s0 += __shfl_xor_sync(0xffffffffu, s0, 1);
        s0 += __shfl_xor_sync(0xffffffffu, s0, 2);
        s1 += __shfl_xor_sync(0xffffffffu, s1, 1);
        s1 += __shfl_xor_sync(0xffffffffu, s1, 2);
        l0 = l0 * al0 + s0;
        l1 = l1 * al1 + s1;
#pragma unroll
        for (int j = 0; j < 8; j++) {
            oa[j][0] *= al0; oa[j][1] *= al0;
            oa[j][2] *= al1; oa[j][3] *= al1;
        }

        // ---- O += P V (3-term); P built from sv fragments in registers
#pragma unroll
        for (int t = 0; t < 4; t++) {
            uint32_t ph[4], pl[4];
            split2(sv[2 * t][0], sv[2 * t][1], ph[0], pl[0]);
            split2(sv[2 * t][2], sv[2 * t][3], ph[1], pl[1]);
            split2(sv[2 * t + 1][0], sv[2 * t + 1][1], ph[2], pl[2]);
            split2(sv[2 * t + 1][2], sv[2 * t + 1][3], ph[3], pl[3]);
            uint32_t vf[4][4];
            uint32_t offs[4];
#pragma unroll
            for (int p = 0; p < 4; p++) {
                uint32_t off = (uint32_t)((p * 16 + b_row) * 128 + t * 32 + b_kb);
                off ^= (off >> 3) & 0x70;
                offs[p] = off;
                ldmx4(vf[p], vh_s + off);
            }
#pragma unroll
            for (int j = 0; j < 8; j++) mma16816(oa[j], ph, &vf[j >> 1][(j & 1) * 2]);
#pragma unroll
            for (int j = 0; j < 8; j++) mma16816(oa[j], pl, &vf[j >> 1][(j & 1) * 2]);
#pragma unroll
            for (int p = 0; p < 4; p++) ldmx4(vf[p], vl_s + offs[p]);
#pragma unroll
            for (int j = 0; j < 8; j++) mma16816(oa[j], ph, &vf[j >> 1][(j & 1) * 2]);
        }
        __syncthreads();
    }

    // ---- epilogue: normalize, split, write to g_xhi/g_xlo in [b,s,d]
    float inv0 = 1.0f / l0, inv1 = 1.0f / l1;
    int bb = bh >> 4, h = bh & 15;
    int r0g = q0 + warp * 16 + (lane >> 2);
    int c0 = (lane & 3) * 2;
#pragma unroll
    for (int j = 0; j < 8; j++) {
        int hd = j * 8 + c0;
        uint32_t hi, lo;
        split2(oa[j][0] * inv0, oa[j][1] * inv0, hi, lo);
        size_t i0 = ((size_t)(bb * SEQ + r0g)) * DMODEL + h * HDIM + hd;
        *(uint32_t*)&g_xhi[i0] = hi;
        *(uint32_t*)&g_xlo[i0] = lo;
        split2(oa[j][2] * inv1, oa[j][3] * inv1, hi, lo);
        size_t i1 = i0 + (size_t)8 * DMODEL;
        *(uint32_t*)&g_xhi[i1] = hi;
        *(uint32_t*)&g_xlo[i1] = lo;
    }
}

// ===================== launch =====================
extern "C" void kernel_launch(void* const* d_in, const int* in_sizes, int n_in,
                              void* d_out, int out_size) {
    (void)in_sizes; (void)n_in; (void)out_size;
    const float* x  = (const float*)d_in[0];
    const float* Wq = (const float*)d_in[1];
    const float* bq = (const float*)d_in[2];
    const float* Wk = (const float*)d_in[3];
    const float* bk = (const float*)d_in[4];
    const float* Wv = (const float*)d_in[5];
    const float* bv = (const float*)d_in[6];
    const float* Wo = (const float*)d_in[7];
    const float* bo = (const float*)d_in[8];
    float* out = (float*)d_out;

    cudaFuncSetAttribute(k_mm, cudaFuncAttributeMaxDynamicSharedMemorySize, MM_SMEM);
    cudaFuncSetAttribute(k_flash2, cudaFuncAttributeMaxDynamicSharedMemorySize, FL2_SMEM);

    k_init_freq<<<1, 512>>>();
    k_pe_split<<<dim3(SEQ / 32, DMODEL / 32, BATCH), dim3(32, 8)>>>(x);
    k_split_w4<<<4096, 256>>>(Wq, Wk, Wv, Wo);

    dim3 ggrid(DMODEL / 128, NTOK / 128);
    k_mm<<<ggrid, 512, MM_SMEM>>>(0, bq, nullptr, 0);
    k_mm<<<ggrid, 512, MM_SMEM>>>(1, bk, nullptr, 1);
    k_mm<<<ggrid, 512, MM_SMEM>>>(2, bv, nullptr, 2);

    k_flash2<<<dim3(SEQ / 128, BATCH * NHEAD), 256, FL2_SMEM>>>();

    k_mm<<<ggrid, 512, MM_SMEM>>>(3, bo, out, 3);
}

// round 13
// speedup vs baseline: 1.0175x; 1.0175x over previous
#include <cuda_runtime.h>
#include <cuda_bf16.h>
#include <cstdint>
#include <math.h>

#define BATCH 4
#define DMODEL 1024
#define SEQ 2048
#define NHEAD 16
#define HDIM 64
#define NTOK (BATCH * SEQ)   // 8192

// ===================== device scratch (no allocation) =====================
__device__ float g_freq[DMODEL / 2];
__device__ __align__(16) __nv_bfloat16 g_xhi[(size_t)NTOK * DMODEL];  // x+PE hi; later attn-out hi
__device__ __align__(16) __nv_bfloat16 g_xlo[(size_t)NTOK * DMODEL];  // x+PE lo; later attn-out lo
__device__ __align__(16) __nv_bfloat16 g_whi[4][(size_t)DMODEL * DMODEL];
__device__ __align__(16) __nv_bfloat16 g_wlo[4][(size_t)DMODEL * DMODEL];
// bf16 hi/lo Q,K ([bh][s][hd], Q pre-scaled by 0.125) and V transposed ([bh][hd][s])
__device__ __align__(16) __nv_bfloat16 g_qhi[(size_t)NTOK * DMODEL];
__device__ __align__(16) __nv_bfloat16 g_qlo[(size_t)NTOK * DMODEL];
__device__ __align__(16) __nv_bfloat16 g_khi[(size_t)NTOK * DMODEL];
__device__ __align__(16) __nv_bfloat16 g_klo[(size_t)NTOK * DMODEL];
__device__ __align__(16) __nv_bfloat16 g_vthi[(size_t)NTOK * DMODEL];
__device__ __align__(16) __nv_bfloat16 g_vtlo[(size_t)NTOK * DMODEL];

// ===================== PTX helpers (family-agnostic) =====================
__device__ __forceinline__ uint32_t smem_u32(const void* p) {
    uint32_t a;
    asm("{ .reg .u64 t; cvta.to.shared.u64 t, %1; cvt.u32.u64 %0, t; }" : "=r"(a) : "l"(p));
    return a;
}
__device__ __forceinline__ void ldmx4(uint32_t* r, uint32_t addr) {
    asm volatile("ldmatrix.sync.aligned.m8n8.x4.shared.b16 {%0,%1,%2,%3}, [%4];"
                 : "=r"(r[0]), "=r"(r[1]), "=r"(r[2]), "=r"(r[3]) : "r"(addr));
}
__device__ __forceinline__ void mma16816(float* d, const uint32_t* a, const uint32_t* b) {
    asm volatile("mma.sync.aligned.m16n8k16.row.col.f32.bf16.bf16.f32 "
                 "{%0,%1,%2,%3}, {%4,%5,%6,%7}, {%8,%9}, {%0,%1,%2,%3};"
                 : "+f"(d[0]), "+f"(d[1]), "+f"(d[2]), "+f"(d[3])
                 : "r"(a[0]), "r"(a[1]), "r"(a[2]), "r"(a[3]), "r"(b[0]), "r"(b[1]));
}
__device__ __forceinline__ void cpa16(uint32_t saddr, const void* g) {
    asm volatile("cp.async.cg.shared.global [%0], [%1], 16;" :: "r"(saddr), "l"(g));
}
#define CP_COMMIT asm volatile("cp.async.commit_group;" ::: "memory")
#define CP_WAIT1 asm volatile("cp.async.wait_group 1;" ::: "memory")
#define CP_WAIT0 asm volatile("cp.async.wait_group 0;" ::: "memory")

// split fp32 pair into packed bf16x2 hi and lo (low half = first arg)
__device__ __forceinline__ void split2(float x0, float x1, uint32_t& hi, uint32_t& lo) {
    __nv_bfloat162 h = __floats2bfloat162_rn(x0, x1);
    hi = *(uint32_t*)&h;
    float r0 = x0 - __bfloat162float(h.x);
    float r1 = x1 - __bfloat162float(h.y);
    __nv_bfloat162 l = __floats2bfloat162_rn(r0, r1);
    lo = *(uint32_t*)&l;
}

// ===================== prep kernels =====================
__global__ void k_init_freq() {
    int i = threadIdx.x;
    if (i < DMODEL / 2)
        g_freq[i] = (float)exp(-(double)(2 * i) * (9.210340371976184 / 1024.0));
}

// x + PE, transpose [B,D,S] -> [B,S,D], write bf16 hi/lo split
__global__ void k_pe_split(const float* __restrict__ x) {
    __shared__ float tile[32][33];
    int b = blockIdx.z, d0 = blockIdx.y * 32, s0 = blockIdx.x * 32;
    int txx = threadIdx.x, tyy = threadIdx.y;
    const float* xb = x + (size_t)b * DMODEL * SEQ;
#pragma unroll
    for (int r = 0; r < 4; r++) {
        int d = d0 + tyy + r * 8, s = s0 + txx;
        float ang = (float)s * g_freq[d >> 1];
        float pe = (d & 1) ? cosf(ang) : sinf(ang);
        tile[tyy + r * 8][txx] = xb[(size_t)d * SEQ + s] + pe;
    }
    __syncthreads();
#pragma unroll
    for (int r = 0; r < 4; r++) {
        int sl = tyy + r * 8;
        float v = tile[txx][sl];
        __nv_bfloat16 hi = __float2bfloat16(v);
        float lo = v - __bfloat162float(hi);
        size_t idx = ((size_t)b * SEQ + s0 + sl) * DMODEL + d0 + txx;
        g_xhi[idx] = hi;
        g_xlo[idx] = __float2bfloat16(lo);
    }
}

// Split all four weight matrices into bf16 hi/lo (one launch)
__global__ void k_split_w4(const float* __restrict__ w0, const float* __restrict__ w1,
                           const float* __restrict__ w2, const float* __restrict__ w3) {
    int wsel = blockIdx.x >> 10;
    const float* w = (wsel == 0) ? w0 : (wsel == 1) ? w1 : (wsel == 2) ? w2 : w3;
    int i = ((blockIdx.x & 1023) * 256 + threadIdx.x) * 4;
    float4 v = *(const float4*)(w + i);
    __nv_bfloat16* hi = g_whi[wsel];
    __nv_bfloat16* lo = g_wlo[wsel];
    float a[4] = {v.x, v.y, v.z, v.w};
#pragma unroll
    for (int j = 0; j < 4; j++) {
        __nv_bfloat16 h = __float2bfloat16(a[j]);
        hi[i + j] = h;
        lo[i + j] = __float2bfloat16(a[j] - __bfloat162float(h));
    }
}

// ===================== HMMA GEMM: C[8192,1024] = A * W^T + bias ==============
// Composite chunks: {Ahi, Alo, Whi, Wlo} x 64-K slice per chunk (64KB), 16 chunks.
// 3-term split: Ahi*Whi + Ahi*Wlo + Alo*Whi; fp32 register accumulators.
// Term-outer MMA order: 8 independent MMAs between accumulator reuse (ILP).
// 3-stage cp.async pipeline (192KB smem), ONE __syncthreads per chunk.
// 512 threads, 16 warps as 4(M) x 4(N): warp tile 32x32, 2x4 m16n8 fragments.
// mode 0: fused QKV (wsel = which = blockIdx.z, bias selected from b0/b1/b2)
// mode 1: output projection (wsel = 3, which = 3, bias = b0, writes outp)
#define MM_STG 65536u
#define MM_SMEM (3 * 65536)

__global__ __launch_bounds__(512) void k_mm(const float* __restrict__ b0,
                                            const float* __restrict__ b1,
                                            const float* __restrict__ b2,
                                            float* __restrict__ outp,
                                            int mode) {
    extern __shared__ char smem[];
    uint32_t sb = smem_u32(smem);
    int tid = threadIdx.x;
    int warp = tid >> 5, lane = tid & 31;
    int wm = warp & 3, wn = warp >> 2;
    int n0 = blockIdx.x * 128, m0 = blockIdx.y * 128;
    int wsel, which;
    const float* bias;
    if (mode == 0) {
        wsel = blockIdx.z; which = wsel;
        bias = (wsel == 0) ? b0 : (wsel == 1) ? b1 : b2;
    } else {
        wsel = 3; which = 3; bias = b0;
    }

    const __nv_bfloat16* WH = g_whi[wsel];
    const __nv_bfloat16* WL = g_wlo[wsel];

    float acc[2][4][4];
#pragma unroll
    for (int mt = 0; mt < 2; mt++)
#pragma unroll
        for (int nt = 0; nt < 4; nt++)
#pragma unroll
            for (int e = 0; e < 4; e++) acc[mt][nt][e] = 0.0f;

    // staging: thread -> (row = it*64 + tid>>3, col16B = tid&7), SW128 swizzle
    int ldr = tid >> 3, ldc = tid & 7;

#define MM_ISSUE(kcv, st) do {                                                      \
        uint32_t bs = sb + (uint32_t)(st) * MM_STG;                                 \
        int _kc = (kcv);                                                            \
        _Pragma("unroll") for (int it = 0; it < 2; it++) {                          \
            int row = it * 64 + ldr;                                                \
            uint32_t off = (uint32_t)(row * 128 + ldc * 16);                        \
            off ^= (off >> 3) & 0x70;                                               \
            size_t ga = (size_t)(m0 + row) * DMODEL + _kc * 64 + ldc * 8;           \
            size_t gb = (size_t)(n0 + row) * DMODEL + _kc * 64 + ldc * 8;           \
            cpa16(bs + off,          g_xhi + ga);                                   \
            cpa16(bs + 16384 + off,  g_xlo + ga);                                   \
            cpa16(bs + 32768 + off,  WH + gb);                                      \
            cpa16(bs + 49152 + off,  WL + gb);                                      \
        }                                                                           \
        CP_COMMIT;                                                                  \
    } while (0)

    // per-thread ldmatrix row/byte components (canonical m16n8k16 fragments)
    int a_row = wm * 32 + (lane & 15);                         // + mt*16
    int a_kb = (lane >> 4) * 16;                               // + k16*32
    int b_row = wn * 32 + (lane & 7) + ((lane >> 4) & 1) * 8;  // + ntp*16
    int b_kb = ((lane >> 3) & 1) * 16;

    MM_ISSUE(0, 0);
    MM_ISSUE(1, 1);

#pragma unroll 1
    for (int kc = 0; kc < 16; kc++) {
        int st = kc % 3;
        if (kc + 1 < 16) CP_WAIT1; else CP_WAIT0;   // this thread's chunk kc arrived
        __syncthreads();                             // visible to all; stage (kc-1)%3 free
        if (kc + 2 < 16) MM_ISSUE(kc + 2, (kc + 2) % 3);
        uint32_t AH = sb + (uint32_t)st * MM_STG;
        uint32_t AL = AH + 16384u, BH = AH + 32768u, BL = AH + 49152u;
#pragma unroll
        for (int k16 = 0; k16 < 4; k16++) {
            int kbyte = k16 * 32;
            uint32_t ah[2][4], al[2][4], bh[2][4], bl[2][4];
#pragma unroll
            for (int mt = 0; mt < 2; mt++) {
                uint32_t off = (uint32_t)((a_row + mt * 16) * 128 + kbyte + a_kb);
                off ^= (off >> 3) & 0x70;
                ldmx4(ah[mt], AH + off);
                ldmx4(al[mt], AL + off);
            }
#pragma unroll
            for (int p = 0; p < 2; p++) {
                uint32_t off = (uint32_t)((b_row + p * 16) * 128 + kbyte + b_kb);
                off ^= (off >> 3) & 0x70;
                ldmx4(bh[p], BH + off);
                ldmx4(bl[p], BL + off);
            }
            // term-outer: 8 independent MMAs between each accumulator's reuse
#pragma unroll
            for (int mt = 0; mt < 2; mt++)
#pragma unroll
                for (int nt = 0; nt < 4; nt++)
                    mma16816(acc[mt][nt], ah[mt], &bh[nt >> 1][(nt & 1) * 2]);
#pragma unroll
            for (int mt = 0; mt < 2; mt++)
#pragma unroll
                for (int nt = 0; nt < 4; nt++)
                    mma16816(acc[mt][nt], ah[mt], &bl[nt >> 1][(nt & 1) * 2]);
#pragma unroll
            for (int mt = 0; mt < 2; mt++)
#pragma unroll
                for (int nt = 0; nt < 4; nt++)
                    mma16816(acc[mt][nt], al[mt], &bh[nt >> 1][(nt & 1) * 2]);
        }
    }

    // ---- epilogue: d0,d1 -> (r0, c0..c0+1); d2,d3 -> (r0+8, ..)
    int r0 = lane >> 2, c0 = (lane & 3) * 2;
    int mbase = m0 + wm * 32, nbase = n0 + wn * 32;
    if (which <= 1) {
        // Q (scaled 0.125) or K -> bf16 hi/lo in [bh][s][hd]
        __nv_bfloat16* HI = which ? g_khi : g_qhi;
        __nv_bfloat16* LO = which ? g_klo : g_qlo;
        float scale = which ? 1.0f : 0.125f;
#pragma unroll
        for (int mt = 0; mt < 2; mt++)
#pragma unroll
            for (int half = 0; half < 2; half++) {
                int row = mbase + mt * 16 + r0 + half * 8;
                int bb2 = row >> 11;
                int sq = row & (SEQ - 1);
#pragma unroll
                for (int nt = 0; nt < 4; nt++) {
                    int jg = nbase + nt * 8 + c0;
                    int h = jg >> 6, hd = jg & 63;
                    float v0 = (acc[mt][nt][half * 2 + 0] + bias[jg + 0]) * scale;
                    float v1 = (acc[mt][nt][half * 2 + 1] + bias[jg + 1]) * scale;
                    uint32_t hi, lo;
                    split2(v0, v1, hi, lo);
                    size_t idx = ((size_t)(bb2 * NHEAD + h) * SEQ + sq) * HDIM + hd;
                    *(uint32_t*)&HI[idx] = hi;
                    *(uint32_t*)&LO[idx] = lo;
                }
            }
    } else if (which == 2) {
        // V -> bf16 hi/lo transposed [bh][hd][s]
#pragma unroll
        for (int mt = 0; mt < 2; mt++)
#pragma unroll
            for (int half = 0; half < 2; half++) {
                int row = mbase + mt * 16 + r0 + half * 8;
                int bb2 = row >> 11;
                int sq = row & (SEQ - 1);
#pragma unroll
                for (int nt = 0; nt < 4; nt++) {
                    int jg = nbase + nt * 8 + c0;
                    int h = jg >> 6, hd = jg & 63;
                    float v0 = acc[mt][nt][half * 2 + 0] + bias[jg + 0];
                    float v1 = acc[mt][nt][half * 2 + 1] + bias[jg + 1];
                    __nv_bfloat16 h0 = __float2bfloat16(v0);
                    __nv_bfloat16 h1 = __float2bfloat16(v1);
                    __nv_bfloat16 l0 = __float2bfloat16(v0 - __bfloat162float(h0));
                    __nv_bfloat16 l1 = __float2bfloat16(v1 - __bfloat162float(h1));
                    size_t tb = ((size_t)(bb2 * NHEAD + h) * HDIM + hd) * SEQ + sq;
                    g_vthi[tb] = h0; g_vtlo[tb] = l0;
                    g_vthi[tb + SEQ] = h1; g_vtlo[tb + SEQ] = l1;
                }
            }
    } else {
        // final projection: out[B, D, S]
#pragma unroll
        for (int mt = 0; mt < 2; mt++)
#pragma unroll
            for (int half = 0; half < 2; half++) {
                int row = mbase + mt * 16 + r0 + half * 8;
                int bb2 = row >> 11;
                int sq = row & (SEQ - 1);
#pragma unroll
                for (int nt = 0; nt < 4; nt++) {
                    int jg = nbase + nt * 8 + c0;
                    outp[((size_t)bb2 * DMODEL + jg) * SEQ + sq] =
                        acc[mt][nt][half * 2 + 0] + bias[jg];
                    outp[((size_t)bb2 * DMODEL + jg + 1) * SEQ + sq] =
                        acc[mt][nt][half * 2 + 1] + bias[jg + 1];
                }
            }
    }
}

// ===================== tensor-core flash attention =====================
// Br=128 (8 warps x m16), Bc=64. S = QhiKhi + QloKhi + QhiKlo (fp32 frags),
// softmax in fragments, P converted to bf16 hi/lo in registers (C->A layout match),
// O += PhiVhi + PloVhi + PhiVlo. K/V tiles cp.async double-buffered.
// smem: stage s at s*32768: KH 8K | KL 8K | VH 8K | VL 8K. Q staged at 0 in prologue.
#define FL2_SMEM 65536
__global__ __launch_bounds__(256) void k_flash2() {
    extern __shared__ char sm2[];
    uint32_t sb = smem_u32(sm2);
    int tid = threadIdx.x;
    int warp = tid >> 5, lane = tid & 31;
    int bh = blockIdx.y;
    int q0 = blockIdx.x * 128;

    const __nv_bfloat16* qh_g = g_qhi + ((size_t)bh * SEQ + q0) * HDIM;
    const __nv_bfloat16* ql_g = g_qlo + ((size_t)bh * SEQ + q0) * HDIM;
    const __nv_bfloat16* kh_g = g_khi + (size_t)bh * SEQ * HDIM;
    const __nv_bfloat16* kl_g = g_klo + (size_t)bh * SEQ * HDIM;
    const __nv_bfloat16* vh_g = g_vthi + (size_t)bh * HDIM * SEQ;
    const __nv_bfloat16* vl_g = g_vtlo + (size_t)bh * HDIM * SEQ;

    // ---- stage Q (hi @0, lo @16384), extract fragments, then free the space
#pragma unroll
    for (int it = 0; it < 4; it++) {
        int c = it * 256 + tid;
        int r = c >> 3, col = c & 7;
        uint32_t off = (uint32_t)(r * 128 + col * 16);
        off ^= (off >> 3) & 0x70;
        *(uint4*)(sm2 + off) = *(const uint4*)(qh_g + (size_t)r * HDIM + col * 8);
        *(uint4*)(sm2 + 16384 + off) = *(const uint4*)(ql_g + (size_t)r * HDIM + col * 8);
    }
    __syncthreads();
    uint32_t qh[4][4], ql[4][4];
    {
        int a_row = warp * 16 + (lane & 15);
        int a_kb = (lane >> 4) * 16;
#pragma unroll
        for (int t = 0; t < 4; t++) {
            uint32_t off = (uint32_t)(a_row * 128 + t * 32 + a_kb);
            off ^= (off >> 3) & 0x70;
            ldmx4(qh[t], sb + off);
            ldmx4(ql[t], sb + 16384 + off);
        }
    }
    __syncthreads();

    int b_row = (lane & 7) + ((lane >> 4) & 1) * 8;   // + pair*16
    int b_kb = ((lane >> 3) & 1) * 16;                // + t*32

#define FL_LOAD(s, kt) do {                                                     \
        uint32_t bs = sb + (uint32_t)(s) * 32768u;                              \
        int kb0 = (kt) * 64;                                                    \
        _Pragma("unroll") for (int it = 0; it < 2; it++) {                      \
            int c = it * 256 + tid;                                             \
            int r = c >> 3, col = c & 7;                                        \
            uint32_t off = (uint32_t)(r * 128 + col * 16);                      \
            off ^= (off >> 3) & 0x70;                                           \
            cpa16(bs + off, kh_g + (size_t)(kb0 + r) * HDIM + col * 8);         \
            cpa16(bs + 8192 + off, kl_g + (size_t)(kb0 + r) * HDIM + col * 8);  \
            cpa16(bs + 16384 + off, vh_g + (size_t)r * SEQ + kb0 + col * 8);    \
            cpa16(bs + 24576 + off, vl_g + (size_t)r * SEQ + kb0 + col * 8);    \
        }                                                                       \
    } while (0)

    float oa[8][4];
#pragma unroll
    for (int j = 0; j < 8; j++)
#pragma unroll
        for (int e = 0; e < 4; e++) oa[j][e] = 0.0f;
    float m0 = -1e30f, m1 = -1e30f, l0 = 0.0f, l1 = 0.0f;

    FL_LOAD(0, 0);
    CP_COMMIT;

#pragma unroll 1
    for (int kt = 0; kt < SEQ / 64; kt++) {
        int s = kt & 1;
        if (kt + 1 < SEQ / 64) {
            FL_LOAD(s ^ 1, kt + 1);
            CP_COMMIT;
            CP_WAIT1;
        } else {
            CP_WAIT0;
        }
        __syncthreads();
        uint32_t kh_s = sb + (uint32_t)s * 32768u;
        uint32_t kl_s = kh_s + 8192u, vh_s = kh_s + 16384u, vl_s = kh_s + 24576u;

        // ---- S = Q K^T (3-term)
        float sv[8][4];
#pragma unroll
        for (int j = 0; j < 8; j++)
#pragma unroll
            for (int e = 0; e < 4; e++) sv[j][e] = 0.0f;
#pragma unroll
        for (int t = 0; t < 4; t++) {
            uint32_t bf_[4][4];
            uint32_t offs[4];
#pragma unroll
            for (int p = 0; p < 4; p++) {
                uint32_t off = (uint32_t)((p * 16 + b_row) * 128 + t * 32 + b_kb);
                off ^= (off >> 3) & 0x70;
                offs[p] = off;
                ldmx4(bf_[p], kh_s + off);
            }
#pragma unroll
            for (int j = 0; j < 8; j++) mma16816(sv[j], qh[t], &bf_[j >> 1][(j & 1) * 2]);
#pragma unroll
            for (int j = 0; j < 8; j++) mma16816(sv[j], ql[t], &bf_[j >> 1][(j & 1) * 2]);
#pragma unroll
            for (int p = 0; p < 4; p++) ldmx4(bf_[p], kl_s + offs[p]);
#pragma unroll
            for (int j = 0; j < 8; j++) mma16816(sv[j], qh[t], &bf_[j >> 1][(j & 1) * 2]);
        }

        // ---- online softmax (rows r0 = d0,d1; r0+8 = d2,d3; reduce over quad)
        float mx0 = sv[0][0], mx1 = sv[0][2];
#pragma unroll
        for (int j = 0; j < 8; j++) {
            mx0 = fmaxf(mx0, fmaxf(sv[j][0], sv[j][1]));
            mx1 = fmaxf(mx1, fmaxf(sv[j][2], sv[j][3]));
        }
        mx0 = fmaxf(mx0, __shfl_xor_sync(0xffffffffu, mx0, 1));
        mx0 = fmaxf(mx0, __shfl_xor_sync(0xffffffffu, mx0, 2));
        mx1 = fmaxf(mx1, __shfl_xor_sync(0xffffffffu, mx1, 1));
        mx1 = fmaxf(mx1, __shfl_xor_sync(0xffffffffu, mx1, 2));
        float mn0 = fmaxf(m0, mx0), mn1 = fmaxf(m1, mx1);
        float al0 = __expf(m0 - mn0), al1 = __expf(m1 - mn1);
        m0 = mn0; m1 = mn1;
        float s0 = 0.0f, s1 = 0.0f;
#pragma unroll
        for (int j = 0; j < 8; j++) {
            sv[j][0] = __expf(sv[j][0] - mn0); s0 += sv[j][0];
            sv[j][1] = __expf(sv[j][1] - mn0); s0 += sv[j][1];
            sv[j][2] = __expf(sv[j][2] - mn1); s1 += sv[j][2];
            sv[j][3] = __expf(sv[j][3] - mn1); s1 += sv[j][3];
        }
        s0 += __shfl_xor_sync(0xffffffffu, s0, 1);
        s0 += __shfl_xor_sync(0xffffffffu, s0, 2);
        s1 += __shfl_xor_sync(0xffffffffu, s1, 1);
        s1 += __shfl_xor_sync(0xffffffffu, s1, 2);
        l0 = l0 * al0 + s0;
        l1 = l1 * al1 + s1;
#pragma unroll
        for (int j = 0; j < 8; j++) {
            oa[j][0] *= al0; oa[j][1] *= al0;
            oa[j][2] *= al1; oa[j][3] *= al1;
        }

        // ---- O += P V (3-term); P built from sv fragments in registers
#pragma unroll
        for (int t = 0; t < 4; t++) {
            uint32_t ph[4], pl[4];
            split2(sv[2 * t][0], sv[2 * t][1], ph[0], pl[0]);
            split2(sv[2 * t][2], sv[2 * t][3], ph[1], pl[1]);
            split2(sv[2 * t + 1][0], sv[2 * t + 1][1], ph[2], pl[2]);
            split2(sv[2 * t + 1][2], sv[2 * t + 1][3], ph[3], pl[3]);
            uint32_t vf[4][4];
            uint32_t offs[4];
#pragma unroll
            for (int p = 0; p < 4; p++) {
                uint32_t off = (uint32_t)((p * 16 + b_row) * 128 + t * 32 + b_kb);
                off ^= (off >> 3) & 0x70;
                offs[p] = off;
                ldmx4(vf[p], vh_s + off);
            }
#pragma unroll
            for (int j = 0; j < 8; j++) mma16816(oa[j], ph, &vf[j >> 1][(j & 1) * 2]);
#pragma unroll
            for (int j = 0; j < 8; j++) mma16816(oa[j], pl, &vf[j >> 1][(j & 1) * 2]);
#pragma unroll
            for (int p = 0; p < 4; p++) ldmx4(vf[p], vl_s + offs[p]);
#pragma unroll
            for (int j = 0; j < 8; j++) mma16816(oa[j], ph, &vf[j >> 1][(j & 1) * 2]);
        }
        __syncthreads();
    }

    // ---- epilogue: normalize, split, write to g_xhi/g_xlo in [b,s,d]
    float inv0 = 1.0f / l0, inv1 = 1.0f / l1;
    int bb = bh >> 4, h = bh & 15;
    int r0g = q0 + warp * 16 + (lane >> 2);
    int c0 = (lane & 3) * 2;
#pragma unroll
    for (int j = 0; j < 8; j++) {
        int hd = j * 8 + c0;
        uint32_t hi, lo;
        split2(oa[j][0] * inv0, oa[j][1] * inv0, hi, lo);
        size_t i0 = ((size_t)(bb * SEQ + r0g)) * DMODEL + h * HDIM + hd;
        *(uint32_t*)&g_xhi[i0] = hi;
        *(uint32_t*)&g_xlo[i0] = lo;
        split2(oa[j][2] * inv1, oa[j][3] * inv1, hi, lo);
        size_t i1 = i0 + (size_t)8 * DMODEL;
        *(uint32_t*)&g_xhi[i1] = hi;
        *(uint32_t*)&g_xlo[i1] = lo;
    }
}

// ===================== launch =====================
extern "C" void kernel_launch(void* const* d_in, const int* in_sizes, int n_in,
                              void* d_out, int out_size) {
    (void)in_sizes; (void)n_in; (void)out_size;
    const float* x  = (const float*)d_in[0];
    const float* Wq = (const float*)d_in[1];
    const float* bq = (const float*)d_in[2];
    const float* Wk = (const float*)d_in[3];
    const float* bk = (const float*)d_in[4];
    const float* Wv = (const float*)d_in[5];
    const float* bv = (const float*)d_in[6];
    const float* Wo = (const float*)d_in[7];
    const float* bo = (const float*)d_in[8];
    float* out = (float*)d_out;

    cudaFuncSetAttribute(k_mm, cudaFuncAttributeMaxDynamicSharedMemorySize, MM_SMEM);
    cudaFuncSetAttribute(k_flash2, cudaFuncAttributeMaxDynamicSharedMemorySize, FL2_SMEM);

    k_init_freq<<<1, 512>>>();
    k_pe_split<<<dim3(SEQ / 32, DMODEL / 32, BATCH), dim3(32, 8)>>>(x);
    k_split_w4<<<4096, 256>>>(Wq, Wk, Wv, Wo);

    // fused QKV: grid.z selects {Q, K, V}
    k_mm<<<dim3(DMODEL / 128, NTOK / 128, 3), 512, MM_SMEM>>>(bq, bk, bv, nullptr, 0);

    k_flash2<<<dim3(SEQ / 128, BATCH * NHEAD), 256, FL2_SMEM>>>();

    k_mm<<<dim3(DMODEL / 128, NTOK / 128, 1), 512, MM_SMEM>>>(bo, nullptr, nullptr, out, 1);
}

// round 14
// speedup vs baseline: 1.0867x; 1.0680x over previous
#include <cuda_runtime.h>
#include <cuda_bf16.h>
#include <cstdint>
#include <math.h>

#define BATCH 4
#define DMODEL 1024
#define SEQ 2048
#define NHEAD 16
#define HDIM 64
#define NTOK (BATCH * SEQ)   // 8192

// ===================== device scratch (no allocation) =====================
__device__ float g_freq[DMODEL / 2];
__device__ __align__(16) __nv_bfloat16 g_xhi[(size_t)NTOK * DMODEL];  // x+PE hi; later attn-out hi
__device__ __align__(16) __nv_bfloat16 g_xlo[(size_t)NTOK * DMODEL];  // x+PE lo; later attn-out lo
__device__ __align__(16) __nv_bfloat16 g_whi[4][(size_t)DMODEL * DMODEL];
__device__ __align__(16) __nv_bfloat16 g_wlo[4][(size_t)DMODEL * DMODEL];
// bf16 hi/lo Q,K ([bh][s][hd], Q pre-scaled by 0.125) and V transposed ([bh][hd][s])
__device__ __align__(16) __nv_bfloat16 g_qhi[(size_t)NTOK * DMODEL];
__device__ __align__(16) __nv_bfloat16 g_qlo[(size_t)NTOK * DMODEL];
__device__ __align__(16) __nv_bfloat16 g_khi[(size_t)NTOK * DMODEL];
__device__ __align__(16) __nv_bfloat16 g_klo[(size_t)NTOK * DMODEL];
__device__ __align__(16) __nv_bfloat16 g_vthi[(size_t)NTOK * DMODEL];
__device__ __align__(16) __nv_bfloat16 g_vtlo[(size_t)NTOK * DMODEL];

// ===================== PTX helpers (family-agnostic) =====================
__device__ __forceinline__ uint32_t smem_u32(const void* p) {
    uint32_t a;
    asm("{ .reg .u64 t; cvta.to.shared.u64 t, %1; cvt.u32.u64 %0, t; }" : "=r"(a) : "l"(p));
    return a;
}
__device__ __forceinline__ void ldmx4(uint32_t* r, uint32_t addr) {
    asm volatile("ldmatrix.sync.aligned.m8n8.x4.shared.b16 {%0,%1,%2,%3}, [%4];"
                 : "=r"(r[0]), "=r"(r[1]), "=r"(r[2]), "=r"(r[3]) : "r"(addr));
}
__device__ __forceinline__ void mma16816(float* d, const uint32_t* a, const uint32_t* b) {
    asm volatile("mma.sync.aligned.m16n8k16.row.col.f32.bf16.bf16.f32 "
                 "{%0,%1,%2,%3}, {%4,%5,%6,%7}, {%8,%9}, {%0,%1,%2,%3};"
                 : "+f"(d[0]), "+f"(d[1]), "+f"(d[2]), "+f"(d[3])
                 : "r"(a[0]), "r"(a[1]), "r"(a[2]), "r"(a[3]), "r"(b[0]), "r"(b[1]));
}
__device__ __forceinline__ void cpa16(uint32_t saddr, const void* g) {
    asm volatile("cp.async.cg.shared.global [%0], [%1], 16;" :: "r"(saddr), "l"(g));
}
#define CP_COMMIT asm volatile("cp.async.commit_group;" ::: "memory")
#define CP_WAIT1 asm volatile("cp.async.wait_group 1;" ::: "memory")
#define CP_WAIT0 asm volatile("cp.async.wait_group 0;" ::: "memory")

// split fp32 pair into packed bf16x2 hi and lo (low half = first arg)
__device__ __forceinline__ void split2(float x0, float x1, uint32_t& hi, uint32_t& lo) {
    __nv_bfloat162 h = __floats2bfloat162_rn(x0, x1);
    hi = *(uint32_t*)&h;
    float r0 = x0 - __bfloat162float(h.x);
    float r1 = x1 - __bfloat162float(h.y);
    __nv_bfloat162 l = __floats2bfloat162_rn(r0, r1);
    lo = *(uint32_t*)&l;
}

// ===================== prep kernels =====================
__global__ void k_init_freq() {
    int i = threadIdx.x;
    if (i < DMODEL / 2)
        g_freq[i] = (float)exp(-(double)(2 * i) * (9.210340371976184 / 1024.0));
}

// x + PE, transpose [B,D,S] -> [B,S,D], write bf16 hi/lo split
__global__ void k_pe_split(const float* __restrict__ x) {
    __shared__ float tile[32][33];
    int b = blockIdx.z, d0 = blockIdx.y * 32, s0 = blockIdx.x * 32;
    int txx = threadIdx.x, tyy = threadIdx.y;
    const float* xb = x + (size_t)b * DMODEL * SEQ;
#pragma unroll
    for (int r = 0; r < 4; r++) {
        int d = d0 + tyy + r * 8, s = s0 + txx;
        float ang = (float)s * g_freq[d >> 1];
        float pe = (d & 1) ? cosf(ang) : sinf(ang);
        tile[tyy + r * 8][txx] = xb[(size_t)d * SEQ + s] + pe;
    }
    __syncthreads();
#pragma unroll
    for (int r = 0; r < 4; r++) {
        int sl = tyy + r * 8;
        float v = tile[txx][sl];
        __nv_bfloat16 hi = __float2bfloat16(v);
        float lo = v - __bfloat162float(hi);
        size_t idx = ((size_t)b * SEQ + s0 + sl) * DMODEL + d0 + txx;
        g_xhi[idx] = hi;
        g_xlo[idx] = __float2bfloat16(lo);
    }
}

// Split all four weight matrices into bf16 hi/lo (one launch)
__global__ void k_split_w4(const float* __restrict__ w0, const float* __restrict__ w1,
                           const float* __restrict__ w2, const float* __restrict__ w3) {
    int wsel = blockIdx.x >> 10;
    const float* w = (wsel == 0) ? w0 : (wsel == 1) ? w1 : (wsel == 2) ? w2 : w3;
    int i = ((blockIdx.x & 1023) * 256 + threadIdx.x) * 4;
    float4 v = *(const float4*)(w + i);
    __nv_bfloat16* hi = g_whi[wsel];
    __nv_bfloat16* lo = g_wlo[wsel];
    float a[4] = {v.x, v.y, v.z, v.w};
#pragma unroll
    for (int j = 0; j < 4; j++) {
        __nv_bfloat16 h = __float2bfloat16(a[j]);
        hi[i + j] = h;
        lo[i + j] = __float2bfloat16(a[j] - __bfloat162float(h));
    }
}

// ===================== HMMA GEMM: C[8192,1024] = A * W^T + bias ==============
// Composite chunks: {Ahi, Alo, Whi, Wlo} x 64-K slice per chunk (64KB), 16 chunks.
// 3-term split: Ahi*Whi + Ahi*Wlo + Alo*Whi; fp32 register accumulators.
// Term-outer MMA order: 8 independent MMAs between accumulator reuse (ILP).
// 3-stage cp.async pipeline (192KB smem), ONE __syncthreads per chunk.
// 512 threads, 16 warps as 4(M) x 4(N): warp tile 32x32, 2x4 m16n8 fragments.
// mode 0: fused QKV (wsel = which = blockIdx.z, bias selected from b0/b1/b2)
// mode 1: output projection (wsel = 3, which = 3, bias = b0, writes outp)
#define MM_STG 65536u
#define MM_SMEM (3 * 65536)

__global__ __launch_bounds__(512) void k_mm(const float* __restrict__ b0,
                                            const float* __restrict__ b1,
                                            const float* __restrict__ b2,
                                            float* __restrict__ outp,
                                            int mode) {
    extern __shared__ char smem[];
    uint32_t sb = smem_u32(smem);
    int tid = threadIdx.x;
    int warp = tid >> 5, lane = tid & 31;
    int wm = warp & 3, wn = warp >> 2;
    int n0 = blockIdx.x * 128, m0 = blockIdx.y * 128;
    int wsel, which;
    const float* bias;
    if (mode == 0) {
        wsel = blockIdx.z; which = wsel;
        bias = (wsel == 0) ? b0 : (wsel == 1) ? b1 : b2;
    } else {
        wsel = 3; which = 3; bias = b0;
    }

    const __nv_bfloat16* WH = g_whi[wsel];
    const __nv_bfloat16* WL = g_wlo[wsel];

    float acc[2][4][4];
#pragma unroll
    for (int mt = 0; mt < 2; mt++)
#pragma unroll
        for (int nt = 0; nt < 4; nt++)
#pragma unroll
            for (int e = 0; e < 4; e++) acc[mt][nt][e] = 0.0f;

    // staging: thread -> (row = it*64 + tid>>3, col16B = tid&7), SW128 swizzle
    int ldr = tid >> 3, ldc = tid & 7;

#define MM_ISSUE(kcv, st) do {                                                      \
        uint32_t bs = sb + (uint32_t)(st) * MM_STG;                                 \
        int _kc = (kcv);                                                            \
        _Pragma("unroll") for (int it = 0; it < 2; it++) {                          \
            int row = it * 64 + ldr;                                                \
            uint32_t off = (uint32_t)(row * 128 + ldc * 16);                        \
            off ^= (off >> 3) & 0x70;                                               \
            size_t ga = (size_t)(m0 + row) * DMODEL + _kc * 64 + ldc * 8;           \
            size_t gb = (size_t)(n0 + row) * DMODEL + _kc * 64 + ldc * 8;           \
            cpa16(bs + off,          g_xhi + ga);                                   \
            cpa16(bs + 16384 + off,  g_xlo + ga);                                   \
            cpa16(bs + 32768 + off,  WH + gb);                                      \
            cpa16(bs + 49152 + off,  WL + gb);                                      \
        }                                                                           \
        CP_COMMIT;                                                                  \
    } while (0)

    // per-thread ldmatrix row/byte components (canonical m16n8k16 fragments)
    int a_row = wm * 32 + (lane & 15);                         // + mt*16
    int a_kb = (lane >> 4) * 16;                               // + k16*32
    int b_row = wn * 32 + (lane & 7) + ((lane >> 4) & 1) * 8;  // + ntp*16
    int b_kb = ((lane >> 3) & 1) * 16;

    MM_ISSUE(0, 0);
    MM_ISSUE(1, 1);

#pragma unroll 1
    for (int kc = 0; kc < 16; kc++) {
        int st = kc % 3;
        if (kc + 1 < 16) CP_WAIT1; else CP_WAIT0;   // this thread's chunk kc arrived
        __syncthreads();                             // visible to all; stage (kc-1)%3 free
        if (kc + 2 < 16) MM_ISSUE(kc + 2, (kc + 2) % 3);
        uint32_t AH = sb + (uint32_t)st * MM_STG;
        uint32_t AL = AH + 16384u, BH = AH + 32768u, BL = AH + 49152u;
#pragma unroll
        for (int k16 = 0; k16 < 4; k16++) {
            int kbyte = k16 * 32;
            uint32_t ah[2][4], al[2][4], bh[2][4], bl[2][4];
#pragma unroll
            for (int mt = 0; mt < 2; mt++) {
                uint32_t off = (uint32_t)((a_row + mt * 16) * 128 + kbyte + a_kb);
                off ^= (off >> 3) & 0x70;
                ldmx4(ah[mt], AH + off);
                ldmx4(al[mt], AL + off);
            }
#pragma unroll
            for (int p = 0; p < 2; p++) {
                uint32_t off = (uint32_t)((b_row + p * 16) * 128 + kbyte + b_kb);
                off ^= (off >> 3) & 0x70;
                ldmx4(bh[p], BH + off);
                ldmx4(bl[p], BL + off);
            }
            // term-outer: 8 independent MMAs between each accumulator's reuse
#pragma unroll
            for (int mt = 0; mt < 2; mt++)
#pragma unroll
                for (int nt = 0; nt < 4; nt++)
                    mma16816(acc[mt][nt], ah[mt], &bh[nt >> 1][(nt & 1) * 2]);
#pragma unroll
            for (int mt = 0; mt < 2; mt++)
#pragma unroll
                for (int nt = 0; nt < 4; nt++)
                    mma16816(acc[mt][nt], ah[mt], &bl[nt >> 1][(nt & 1) * 2]);
#pragma unroll
            for (int mt = 0; mt < 2; mt++)
#pragma unroll
                for (int nt = 0; nt < 4; nt++)
                    mma16816(acc[mt][nt], al[mt], &bh[nt >> 1][(nt & 1) * 2]);
        }
    }

    // ---- epilogue: d0,d1 -> (r0, c0..c0+1); d2,d3 -> (r0+8, ..)
    int r0 = lane >> 2, c0 = (lane & 3) * 2;
    int mbase = m0 + wm * 32, nbase = n0 + wn * 32;
    if (which <= 1) {
        // Q (scaled 0.125) or K -> bf16 hi/lo in [bh][s][hd]
        __nv_bfloat16* HI = which ? g_khi : g_qhi;
        __nv_bfloat16* LO = which ? g_klo : g_qlo;
        float scale = which ? 1.0f : 0.125f;
#pragma unroll
        for (int mt = 0; mt < 2; mt++)
#pragma unroll
            for (int half = 0; half < 2; half++) {
                int row = mbase + mt * 16 + r0 + half * 8;
                int bb2 = row >> 11;
                int sq = row & (SEQ - 1);
#pragma unroll
                for (int nt = 0; nt < 4; nt++) {
                    int jg = nbase + nt * 8 + c0;
                    int h = jg >> 6, hd = jg & 63;
                    float v0 = (acc[mt][nt][half * 2 + 0] + bias[jg + 0]) * scale;
                    float v1 = (acc[mt][nt][half * 2 + 1] + bias[jg + 1]) * scale;
                    uint32_t hi, lo;
                    split2(v0, v1, hi, lo);
                    size_t idx = ((size_t)(bb2 * NHEAD + h) * SEQ + sq) * HDIM + hd;
                    *(uint32_t*)&HI[idx] = hi;
                    *(uint32_t*)&LO[idx] = lo;
                }
            }
    } else if (which == 2) {
        // V -> bf16 hi/lo transposed [bh][hd][s]
#pragma unroll
        for (int mt = 0; mt < 2; mt++)
#pragma unroll
            for (int half = 0; half < 2; half++) {
                int row = mbase + mt * 16 + r0 + half * 8;
                int bb2 = row >> 11;
                int sq = row & (SEQ - 1);
#pragma unroll
                for (int nt = 0; nt < 4; nt++) {
                    int jg = nbase + nt * 8 + c0;
                    int h = jg >> 6, hd = jg & 63;
                    float v0 = acc[mt][nt][half * 2 + 0] + bias[jg + 0];
                    float v1 = acc[mt][nt][half * 2 + 1] + bias[jg + 1];
                    __nv_bfloat16 h0 = __float2bfloat16(v0);
                    __nv_bfloat16 h1 = __float2bfloat16(v1);
                    __nv_bfloat16 l0 = __float2bfloat16(v0 - __bfloat162float(h0));
                    __nv_bfloat16 l1 = __float2bfloat16(v1 - __bfloat162float(h1));
                    size_t tb = ((size_t)(bb2 * NHEAD + h) * HDIM + hd) * SEQ + sq;
                    g_vthi[tb] = h0; g_vtlo[tb] = l0;
                    g_vthi[tb + SEQ] = h1; g_vtlo[tb + SEQ] = l1;
                }
            }
    } else {
        // final projection: out[B, D, S]
#pragma unroll
        for (int mt = 0; mt < 2; mt++)
#pragma unroll
            for (int half = 0; half < 2; half++) {
                int row = mbase + mt * 16 + r0 + half * 8;
                int bb2 = row >> 11;
                int sq = row & (SEQ - 1);
#pragma unroll
                for (int nt = 0; nt < 4; nt++) {
                    int jg = nbase + nt * 8 + c0;
                    outp[((size_t)bb2 * DMODEL + jg) * SEQ + sq] =
                        acc[mt][nt][half * 2 + 0] + bias[jg];
                    outp[((size_t)bb2 * DMODEL + jg + 1) * SEQ + sq] =
                        acc[mt][nt][half * 2 + 1] + bias[jg + 1];
                }
            }
    }
}

// ===================== tensor-core flash attention (2 CTAs/SM) =====================
// Br=128 (8 warps x m16), Bc=64. S = QhiKhi + QloKhi + QhiKlo (fp32 frags),
// softmax in fragments, P hi/lo in registers, O += PhiVhi + PloVhi + PhiVlo.
// smem (96KB/CTA -> 2 CTAs/SM): stage s at s*32768 (KH|KL|VH|VL 8K each),
// Q-hi persistent @65536 (16K), Q-lo persistent @81920 (16K).
// Q-hi fragments live in registers; Q-lo fragments re-ldmatrix'd per tile to
// keep regs <= 128 for 2-CTA occupancy.
#define FL2_SMEM 98304
__global__ void __launch_bounds__(256, 2) k_flash2() {
    extern __shared__ char sm2[];
    uint32_t sb = smem_u32(sm2);
    int tid = threadIdx.x;
    int warp = tid >> 5, lane = tid & 31;
    int bh = blockIdx.y;
    int q0 = blockIdx.x * 128;

    const __nv_bfloat16* qh_g = g_qhi + ((size_t)bh * SEQ + q0) * HDIM;
    const __nv_bfloat16* ql_g = g_qlo + ((size_t)bh * SEQ + q0) * HDIM;
    const __nv_bfloat16* kh_g = g_khi + (size_t)bh * SEQ * HDIM;
    const __nv_bfloat16* kl_g = g_klo + (size_t)bh * SEQ * HDIM;
    const __nv_bfloat16* vh_g = g_vthi + (size_t)bh * HDIM * SEQ;
    const __nv_bfloat16* vl_g = g_vtlo + (size_t)bh * HDIM * SEQ;

#define FL_LOAD(s, kt) do {                                                     \
        uint32_t bs = sb + (uint32_t)(s) * 32768u;                              \
        int kb0 = (kt) * 64;                                                    \
        _Pragma("unroll") for (int it = 0; it < 2; it++) {                      \
            int c = it * 256 + tid;                                             \
            int r = c >> 3, col = c & 7;                                        \
            uint32_t off = (uint32_t)(r * 128 + col * 16);                      \
            off ^= (off >> 3) & 0x70;                                           \
            cpa16(bs + off, kh_g + (size_t)(kb0 + r) * HDIM + col * 8);         \
            cpa16(bs + 8192 + off, kl_g + (size_t)(kb0 + r) * HDIM + col * 8);  \
            cpa16(bs + 16384 + off, vh_g + (size_t)r * SEQ + kb0 + col * 8);    \
            cpa16(bs + 24576 + off, vl_g + (size_t)r * SEQ + kb0 + col * 8);    \
        }                                                                       \
    } while (0)

    // kick off first KV stage before Q staging (overlap)
    FL_LOAD(0, 0);
    CP_COMMIT;

    // ---- stage Q persistently: hi @65536, lo @81920
#pragma unroll
    for (int it = 0; it < 4; it++) {
        int c = it * 256 + tid;
        int r = c >> 3, col = c & 7;
        uint32_t off = (uint32_t)(r * 128 + col * 16);
        off ^= (off >> 3) & 0x70;
        *(uint4*)(sm2 + 65536 + off) = *(const uint4*)(qh_g + (size_t)r * HDIM + col * 8);
        *(uint4*)(sm2 + 81920 + off) = *(const uint4*)(ql_g + (size_t)r * HDIM + col * 8);
    }
    __syncthreads();

    // Q-hi fragments in registers (persistent); Q-lo re-loaded per tile
    int a_row = warp * 16 + (lane & 15);
    int a_kb = (lane >> 4) * 16;
    uint32_t qh[4][4];
#pragma unroll
    for (int t = 0; t < 4; t++) {
        uint32_t off = (uint32_t)(a_row * 128 + t * 32 + a_kb);
        off ^= (off >> 3) & 0x70;
        ldmx4(qh[t], sb + 65536u + off);
    }

    int b_row = (lane & 7) + ((lane >> 4) & 1) * 8;   // + pair*16
    int b_kb = ((lane >> 3) & 1) * 16;                // + t*32

    float oa[8][4];
#pragma unroll
    for (int j = 0; j < 8; j++)
#pragma unroll
        for (int e = 0; e < 4; e++) oa[j][e] = 0.0f;
    float m0 = -1e30f, m1 = -1e30f, l0 = 0.0f, l1 = 0.0f;

#pragma unroll 1
    for (int kt = 0; kt < SEQ / 64; kt++) {
        int s = kt & 1;
        if (kt + 1 < SEQ / 64) {
            FL_LOAD(s ^ 1, kt + 1);
            CP_COMMIT;
            CP_WAIT1;
        } else {
            CP_WAIT0;
        }
        __syncthreads();
        uint32_t kh_s = sb + (uint32_t)s * 32768u;
        uint32_t kl_s = kh_s + 8192u, vh_s = kh_s + 16384u, vl_s = kh_s + 24576u;

        // ---- S = Q K^T (3-term; same accumulation order as before)
        float sv[8][4];
#pragma unroll
        for (int j = 0; j < 8; j++)
#pragma unroll
            for (int e = 0; e < 4; e++) sv[j][e] = 0.0f;
#pragma unroll
        for (int t = 0; t < 4; t++) {
            uint32_t bf_[4][4];
            uint32_t offs[4];
#pragma unroll
            for (int p = 0; p < 4; p++) {
                uint32_t off = (uint32_t)((p * 16 + b_row) * 128 + t * 32 + b_kb);
                off ^= (off >> 3) & 0x70;
                offs[p] = off;
                ldmx4(bf_[p], kh_s + off);
            }
            // Q-lo fragment for this t (from persistent smem)
            uint32_t ql_t[4];
            {
                uint32_t qoff = (uint32_t)(a_row * 128 + t * 32 + a_kb);
                qoff ^= (qoff >> 3) & 0x70;
                ldmx4(ql_t, sb + 81920u + qoff);
            }
#pragma unroll
            for (int j = 0; j < 8; j++) mma16816(sv[j], qh[t], &bf_[j >> 1][(j & 1) * 2]);
#pragma unroll
            for (int j = 0; j < 8; j++) mma16816(sv[j], ql_t, &bf_[j >> 1][(j & 1) * 2]);
#pragma unroll
            for (int p = 0; p < 4; p++) ldmx4(bf_[p], kl_s + offs[p]);
#pragma unroll
            for (int j = 0; j < 8; j++) mma16816(sv[j], qh[t], &bf_[j >> 1][(j & 1) * 2]);
        }

        // ---- online softmax (rows r0 = d0,d1; r0+8 = d2,d3; reduce over quad)
        float mx0 = sv[0][0], mx1 = sv[0][2];
#pragma unroll
        for (int j = 0; j < 8; j++) {
            mx0 = fmaxf(mx0, fmaxf(sv[j][0], sv[j][1]));
            mx1 = fmaxf(mx1, fmaxf(sv[j][2], sv[j][3]));
        }
        mx0 = fmaxf(mx0, __shfl_xor_sync(0xffffffffu, mx0, 1));
        mx0 = fmaxf(mx0, __shfl_xor_sync(0xffffffffu, mx0, 2));
        mx1 = fmaxf(mx1, __shfl_xor_sync(0xffffffffu, mx1, 1));
        mx1 = fmaxf(mx1, __shfl_xor_sync(0xffffffffu, mx1, 2));
        float mn0 = fmaxf(m0, mx0), mn1 = fmaxf(m1, mx1);
        float al0 = __expf(m0 - mn0), al1 = __expf(m1 - mn1);
        m0 = mn0; m1 = mn1;
        float s0 = 0.0f, s1 = 0.0f;
#pragma unroll
        for (int j = 0; j < 8; j++) {
            sv[j][0] = __expf(sv[j][0] - mn0); s0 += sv[j][0];
            sv[j][1] = __expf(sv[j][1] - mn0); s0 += sv[j][1];
            sv[j][2] = __expf(sv[j][2] - mn1); s1 += sv[j][2];
            sv[j][3] = __expf(sv[j][3] - mn1); s1 += sv[j][3];
        }
        s0 += __shfl_xor_sync(0xffffffffu, s0, 1);
        s0 += __shfl_xor_sync(0xffffffffu, s0, 2);
        s1 += __shfl_xor_sync(0xffffffffu, s1, 1);
        s1 += __shfl_xor_sync(0xffffffffu, s1, 2);
        l0 = l0 * al0 + s0;
        l1 = l1 * al1 + s1;
#pragma unroll
        for (int j = 0; j < 8; j++) {
            oa[j][0] *= al0; oa[j][1] *= al0;
            oa[j][2] *= al1; oa[j][3] *= al1;
        }

        // ---- O += P V (3-term); P built from sv fragments in registers
#pragma unroll
        for (int t = 0; t < 4; t++) {
            uint32_t ph[4], pl[4];
            split2(sv[2 * t][0], sv[2 * t][1], ph[0], pl[0]);
            split2(sv[2 * t][2], sv[2 * t][3], ph[1], pl[1]);
            split2(sv[2 * t + 1][0], sv[2 * t + 1][1], ph[2], pl[2]);
            split2(sv[2 * t + 1][2], sv[2 * t + 1][3], ph[3], pl[3]);
            uint32_t vf[4][4];
            uint32_t offs[4];
#pragma unroll
            for (int p = 0; p < 4; p++) {
                uint32_t off = (uint32_t)((p * 16 + b_row) * 128 + t * 32 + b_kb);
                off ^= (off >> 3) & 0x70;
                offs[p] = off;
                ldmx4(vf[p], vh_s + off);
            }
#pragma unroll
            for (int j = 0; j < 8; j++) mma16816(oa[j], ph, &vf[j >> 1][(j & 1) * 2]);
#pragma unroll
            for (int j = 0; j < 8; j++) mma16816(oa[j], pl, &vf[j >> 1][(j & 1) * 2]);
#pragma unroll
            for (int p = 0; p < 4; p++) ldmx4(vf[p], vl_s + offs[p]);
#pragma unroll
            for (int j = 0; j < 8; j++) mma16816(oa[j], ph, &vf[j >> 1][(j & 1) * 2]);
        }
        __syncthreads();
    }

    // ---- epilogue: normalize, split, write to g_xhi/g_xlo in [b,s,d]
    float inv0 = 1.0f / l0, inv1 = 1.0f / l1;
    int bb = bh >> 4, h = bh & 15;
    int r0g = q0 + warp * 16 + (lane >> 2);
    int c0 = (lane & 3) * 2;
#pragma unroll
    for (int j = 0; j < 8; j++) {
        int hd = j * 8 + c0;
        uint32_t hi, lo;
        split2(oa[j][0] * inv0, oa[j][1] * inv0, hi, lo);
        size_t i0 = ((size_t)(bb * SEQ + r0g)) * DMODEL + h * HDIM + hd;
        *(uint32_t*)&g_xhi[i0] = hi;
        *(uint32_t*)&g_xlo[i0] = lo;
        split2(oa[j][2] * inv1, oa[j][3] * inv1, hi, lo);
        size_t i1 = i0 + (size_t)8 * DMODEL;
        *(uint32_t*)&g_xhi[i1] = hi;
        *(uint32_t*)&g_xlo[i1] = lo;
    }
}

// ===================== launch =====================
extern "C" void kernel_launch(void* const* d_in, const int* in_sizes, int n_in,
                              void* d_out, int out_size) {
    (void)in_sizes; (void)n_in; (void)out_size;
    const float* x  = (const float*)d_in[0];
    const float* Wq = (const float*)d_in[1];
    const float* bq = (const float*)d_in[2];
    const float* Wk = (const float*)d_in[3];
    const float* bk = (const float*)d_in[4];
    const float* Wv = (const float*)d_in[5];
    const float* bv = (const float*)d_in[6];
    const float* Wo = (const float*)d_in[7];
    const float* bo = (const float*)d_in[8];
    float* out = (float*)d_out;

    cudaFuncSetAttribute(k_mm, cudaFuncAttributeMaxDynamicSharedMemorySize, MM_SMEM);
    cudaFuncSetAttribute(k_flash2, cudaFuncAttributeMaxDynamicSharedMemorySize, FL2_SMEM);

    k_init_freq<<<1, 512>>>();
    k_pe_split<<<dim3(SEQ / 32, DMODEL / 32, BATCH), dim3(32, 8)>>>(x);
    k_split_w4<<<4096, 256>>>(Wq, Wk, Wv, Wo);

    // fused QKV: grid.z selects {Q, K, V}
    k_mm<<<dim3(DMODEL / 128, NTOK / 128, 3), 512, MM_SMEM>>>(bq, bk, bv, nullptr, 0);

    k_flash2<<<dim3(SEQ / 128, BATCH * NHEAD), 256, FL2_SMEM>>>();

    k_mm<<<dim3(DMODEL / 128, NTOK / 128, 1), 512, MM_SMEM>>>(bo, nullptr, nullptr, out, 1);
}

// round 15
// speedup vs baseline: 1.1135x; 1.0247x over previous
#include <cuda_runtime.h>
#include <cuda_bf16.h>
#include <cstdint>
#include <math.h>

#define BATCH 4
#define DMODEL 1024
#define SEQ 2048
#define NHEAD 16
#define HDIM 64
#define NTOK (BATCH * SEQ)   // 8192

// ===================== device scratch (no allocation) =====================
__device__ float g_freq[DMODEL / 2];
__device__ __align__(16) __nv_bfloat16 g_xhi[(size_t)NTOK * DMODEL];  // x+PE hi; later attn-out hi
__device__ __align__(16) __nv_bfloat16 g_xlo[(size_t)NTOK * DMODEL];  // x+PE lo; later attn-out lo
__device__ __align__(16) __nv_bfloat16 g_whi[4][(size_t)DMODEL * DMODEL];
__device__ __align__(16) __nv_bfloat16 g_wlo[4][(size_t)DMODEL * DMODEL];
// bf16 hi/lo Q,K ([bh][s][hd], Q pre-scaled by 0.125) and V transposed ([bh][hd][s])
__device__ __align__(16) __nv_bfloat16 g_qhi[(size_t)NTOK * DMODEL];
__device__ __align__(16) __nv_bfloat16 g_qlo[(size_t)NTOK * DMODEL];
__device__ __align__(16) __nv_bfloat16 g_khi[(size_t)NTOK * DMODEL];
__device__ __align__(16) __nv_bfloat16 g_klo[(size_t)NTOK * DMODEL];
__device__ __align__(16) __nv_bfloat16 g_vthi[(size_t)NTOK * DMODEL];
__device__ __align__(16) __nv_bfloat16 g_vtlo[(size_t)NTOK * DMODEL];

// ===================== PTX helpers (family-agnostic) =====================
__device__ __forceinline__ uint32_t smem_u32(const void* p) {
    uint32_t a;
    asm("{ .reg .u64 t; cvta.to.shared.u64 t, %1; cvt.u32.u64 %0, t; }" : "=r"(a) : "l"(p));
    return a;
}
__device__ __forceinline__ void ldmx4(uint32_t* r, uint32_t addr) {
    asm volatile("ldmatrix.sync.aligned.m8n8.x4.shared.b16 {%0,%1,%2,%3}, [%4];"
                 : "=r"(r[0]), "=r"(r[1]), "=r"(r[2]), "=r"(r[3]) : "r"(addr));
}
__device__ __forceinline__ void mma16816(float* d, const uint32_t* a, const uint32_t* b) {
    asm volatile("mma.sync.aligned.m16n8k16.row.col.f32.bf16.bf16.f32 "
                 "{%0,%1,%2,%3}, {%4,%5,%6,%7}, {%8,%9}, {%0,%1,%2,%3};"
                 : "+f"(d[0]), "+f"(d[1]), "+f"(d[2]), "+f"(d[3])
                 : "r"(a[0]), "r"(a[1]), "r"(a[2]), "r"(a[3]), "r"(b[0]), "r"(b[1]));
}
__device__ __forceinline__ void cpa16(uint32_t saddr, const void* g) {
    asm volatile("cp.async.cg.shared.global [%0], [%1], 16;" :: "r"(saddr), "l"(g));
}
#define CP_COMMIT asm volatile("cp.async.commit_group;" ::: "memory")
#define CP_WAIT1 asm volatile("cp.async.wait_group 1;" ::: "memory")
#define CP_WAIT0 asm volatile("cp.async.wait_group 0;" ::: "memory")

// split fp32 pair into packed bf16x2 hi and lo (low half = first arg)
__device__ __forceinline__ void split2(float x0, float x1, uint32_t& hi, uint32_t& lo) {
    __nv_bfloat162 h = __floats2bfloat162_rn(x0, x1);
    hi = *(uint32_t*)&h;
    float r0 = x0 - __bfloat162float(h.x);
    float r1 = x1 - __bfloat162float(h.y);
    __nv_bfloat162 l = __floats2bfloat162_rn(r0, r1);
    lo = *(uint32_t*)&l;
}

// ===================== prep kernels =====================
__global__ void k_init_freq() {
    int i = threadIdx.x;
    if (i < DMODEL / 2)
        g_freq[i] = (float)exp(-(double)(2 * i) * (9.210340371976184 / 1024.0));
}

// x + PE, transpose [B,D,S] -> [B,S,D], write bf16 hi/lo split
__global__ void k_pe_split(const float* __restrict__ x) {
    __shared__ float tile[32][33];
    int b = blockIdx.z, d0 = blockIdx.y * 32, s0 = blockIdx.x * 32;
    int txx = threadIdx.x, tyy = threadIdx.y;
    const float* xb = x + (size_t)b * DMODEL * SEQ;
#pragma unroll
    for (int r = 0; r < 4; r++) {
        int d = d0 + tyy + r * 8, s = s0 + txx;
        float ang = (float)s * g_freq[d >> 1];
        float pe = (d & 1) ? cosf(ang) : sinf(ang);
        tile[tyy + r * 8][txx] = xb[(size_t)d * SEQ + s] + pe;
    }
    __syncthreads();
#pragma unroll
    for (int r = 0; r < 4; r++) {
        int sl = tyy + r * 8;
        float v = tile[txx][sl];
        __nv_bfloat16 hi = __float2bfloat16(v);
        float lo = v - __bfloat162float(hi);
        size_t idx = ((size_t)b * SEQ + s0 + sl) * DMODEL + d0 + txx;
        g_xhi[idx] = hi;
        g_xlo[idx] = __float2bfloat16(lo);
    }
}

// Split all four weight matrices into bf16 hi/lo (one launch)
__global__ void k_split_w4(const float* __restrict__ w0, const float* __restrict__ w1,
                           const float* __restrict__ w2, const float* __restrict__ w3) {
    int wsel = blockIdx.x >> 10;
    const float* w = (wsel == 0) ? w0 : (wsel == 1) ? w1 : (wsel == 2) ? w2 : w3;
    int i = ((blockIdx.x & 1023) * 256 + threadIdx.x) * 4;
    float4 v = *(const float4*)(w + i);
    __nv_bfloat16* hi = g_whi[wsel];
    __nv_bfloat16* lo = g_wlo[wsel];
    float a[4] = {v.x, v.y, v.z, v.w};
#pragma unroll
    for (int j = 0; j < 4; j++) {
        __nv_bfloat16 h = __float2bfloat16(a[j]);
        hi[i + j] = h;
        lo[i + j] = __float2bfloat16(a[j] - __bfloat162float(h));
    }
}

// ===================== HMMA GEMM: C[8192,1024] = A * W^T + bias ==============
// CTA tile 128(M) x 64(N), 256 threads, 2 CTAs/SM (96KB smem each).
// Composite chunks: {Ahi, Alo(128r), Whi, Wlo(64r)} x 64-K slice (48KB), 16 chunks.
// 3-term split: Ahi*Whi + Ahi*Wlo + Alo*Whi; fp32 register accumulators.
// 2-stage double buffer, 2 barriers/chunk (cross-CTA overlap hides them).
// 8 warps as 4(M) x 2(N): warp tile 32x32, 2x4 m16n8 fragments.
// mode 0: fused QKV (wsel = which = blockIdx.z); mode 1: out-proj (wsel=3).
#define MM_STG 49152u
#define MM_SMEM (2 * 49152)

__global__ void __launch_bounds__(256, 2) k_mm(const float* __restrict__ b0,
                                               const float* __restrict__ b1,
                                               const float* __restrict__ b2,
                                               float* __restrict__ outp,
                                               int mode) {
    extern __shared__ char smem[];
    uint32_t sb = smem_u32(smem);
    int tid = threadIdx.x;
    int warp = tid >> 5, lane = tid & 31;
    int wm = warp & 3, wn = warp >> 2;
    int n0 = blockIdx.x * 64, m0 = blockIdx.y * 128;
    int wsel, which;
    const float* bias;
    if (mode == 0) {
        wsel = blockIdx.z; which = wsel;
        bias = (wsel == 0) ? b0 : (wsel == 1) ? b1 : b2;
    } else {
        wsel = 3; which = 3; bias = b0;
    }

    const __nv_bfloat16* WH = g_whi[wsel];
    const __nv_bfloat16* WL = g_wlo[wsel];

    float acc[2][4][4];
#pragma unroll
    for (int mt = 0; mt < 2; mt++)
#pragma unroll
        for (int nt = 0; nt < 4; nt++)
#pragma unroll
            for (int e = 0; e < 4; e++) acc[mt][nt][e] = 0.0f;

    // staging: thread -> (row = it*32 + tid>>3, col16B = tid&7), SW128 swizzle
    int ldr = tid >> 3, ldc = tid & 7;

#define MM_ISSUE(kcv, st) do {                                                      \
        uint32_t bs = sb + (uint32_t)(st) * MM_STG;                                 \
        int _kc = (kcv);                                                            \
        _Pragma("unroll") for (int it = 0; it < 4; it++) {                          \
            int row = it * 32 + ldr;                                                \
            uint32_t off = (uint32_t)(row * 128 + ldc * 16);                        \
            off ^= (off >> 3) & 0x70;                                               \
            size_t ga = (size_t)(m0 + row) * DMODEL + _kc * 64 + ldc * 8;           \
            cpa16(bs + off,          g_xhi + ga);                                   \
            cpa16(bs + 16384 + off,  g_xlo + ga);                                   \
        }                                                                           \
        _Pragma("unroll") for (int it = 0; it < 2; it++) {                          \
            int row = it * 32 + ldr;                                                \
            uint32_t off = (uint32_t)(row * 128 + ldc * 16);                        \
            off ^= (off >> 3) & 0x70;                                               \
            size_t gb = (size_t)(n0 + row) * DMODEL + _kc * 64 + ldc * 8;           \
            cpa16(bs + 32768 + off,  WH + gb);                                      \
            cpa16(bs + 40960 + off,  WL + gb);                                      \
        }                                                                           \
        CP_COMMIT;                                                                  \
    } while (0)

    // per-thread ldmatrix row/byte components (canonical m16n8k16 fragments)
    int a_row = wm * 32 + (lane & 15);                         // + mt*16
    int a_kb = (lane >> 4) * 16;                               // + k16*32
    int b_row = wn * 32 + (lane & 7) + ((lane >> 4) & 1) * 8;  // + p*16
    int b_kb = ((lane >> 3) & 1) * 16;

    MM_ISSUE(0, 0);
    MM_ISSUE(1, 1);

#pragma unroll 1
    for (int kc = 0; kc < 16; kc++) {
        int st = kc & 1;
        if (kc + 1 < 16) CP_WAIT1; else CP_WAIT0;   // chunk kc arrived
        __syncthreads();
        uint32_t AH = sb + (uint32_t)st * MM_STG;
        uint32_t AL = AH + 16384u, BH = AH + 32768u, BL = AH + 40960u;
#pragma unroll
        for (int k16 = 0; k16 < 4; k16++) {
            int kbyte = k16 * 32;
            uint32_t ah[2][4], al[2][4], bh[2][4], bl[2][4];
#pragma unroll
            for (int mt = 0; mt < 2; mt++) {
                uint32_t off = (uint32_t)((a_row + mt * 16) * 128 + kbyte + a_kb);
                off ^= (off >> 3) & 0x70;
                ldmx4(ah[mt], AH + off);
                ldmx4(al[mt], AL + off);
            }
#pragma unroll
            for (int p = 0; p < 2; p++) {
                uint32_t off = (uint32_t)((b_row + p * 16) * 128 + kbyte + b_kb);
                off ^= (off >> 3) & 0x70;
                ldmx4(bh[p], BH + off);
                ldmx4(bl[p], BL + off);
            }
            // term-outer: 8 independent MMAs between each accumulator's reuse
#pragma unroll
            for (int mt = 0; mt < 2; mt++)
#pragma unroll
                for (int nt = 0; nt < 4; nt++)
                    mma16816(acc[mt][nt], ah[mt], &bh[nt >> 1][(nt & 1) * 2]);
#pragma unroll
            for (int mt = 0; mt < 2; mt++)
#pragma unroll
                for (int nt = 0; nt < 4; nt++)
                    mma16816(acc[mt][nt], ah[mt], &bl[nt >> 1][(nt & 1) * 2]);
#pragma unroll
            for (int mt = 0; mt < 2; mt++)
#pragma unroll
                for (int nt = 0; nt < 4; nt++)
                    mma16816(acc[mt][nt], al[mt], &bh[nt >> 1][(nt & 1) * 2]);
        }
        __syncthreads();                             // all done reading stage st
        if (kc + 2 < 16) MM_ISSUE(kc + 2, st);       // safe to overwrite st
    }

    // ---- epilogue: d0,d1 -> (r0, c0..c0+1); d2,d3 -> (r0+8, ..)
    int r0 = lane >> 2, c0 = (lane & 3) * 2;
    int mbase = m0 + wm * 32, nbase = n0 + wn * 32;
    if (which <= 1) {
        // Q (scaled 0.125) or K -> bf16 hi/lo in [bh][s][hd]
        __nv_bfloat16* HI = which ? g_khi : g_qhi;
        __nv_bfloat16* LO = which ? g_klo : g_qlo;
        float scale = which ? 1.0f : 0.125f;
#pragma unroll
        for (int mt = 0; mt < 2; mt++)
#pragma unroll
            for (int half = 0; half < 2; half++) {
                int row = mbase + mt * 16 + r0 + half * 8;
                int bb2 = row >> 11;
                int sq = row & (SEQ - 1);
#pragma unroll
                for (int nt = 0; nt < 4; nt++) {
                    int jg = nbase + nt * 8 + c0;
                    int h = jg >> 6, hd = jg & 63;
                    float v0 = (acc[mt][nt][half * 2 + 0] + bias[jg + 0]) * scale;
                    float v1 = (acc[mt][nt][half * 2 + 1] + bias[jg + 1]) * scale;
                    uint32_t hi, lo;
                    split2(v0, v1, hi, lo);
                    size_t idx = ((size_t)(bb2 * NHEAD + h) * SEQ + sq) * HDIM + hd;
                    *(uint32_t*)&HI[idx] = hi;
                    *(uint32_t*)&LO[idx] = lo;
                }
            }
    } else if (which == 2) {
        // V -> bf16 hi/lo transposed [bh][hd][s]
#pragma unroll
        for (int mt = 0; mt < 2; mt++)
#pragma unroll
            for (int half = 0; half < 2; half++) {
                int row = mbase + mt * 16 + r0 + half * 8;
                int bb2 = row >> 11;
                int sq = row & (SEQ - 1);
#pragma unroll
                for (int nt = 0; nt < 4; nt++) {
                    int jg = nbase + nt * 8 + c0;
                    int h = jg >> 6, hd = jg & 63;
                    float v0 = acc[mt][nt][half * 2 + 0] + bias[jg + 0];
                    float v1 = acc[mt][nt][half * 2 + 1] + bias[jg + 1];
                    __nv_bfloat16 h0 = __float2bfloat16(v0);
                    __nv_bfloat16 h1 = __float2bfloat16(v1);
                    __nv_bfloat16 l0 = __float2bfloat16(v0 - __bfloat162float(h0));
                    __nv_bfloat16 l1 = __float2bfloat16(v1 - __bfloat162float(h1));
                    size_t tb = ((size_t)(bb2 * NHEAD + h) * HDIM + hd) * SEQ + sq;
                    g_vthi[tb] = h0; g_vtlo[tb] = l0;
                    g_vthi[tb + SEQ] = h1; g_vtlo[tb + SEQ] = l1;
                }
            }
    } else {
        // final projection: out[B, D, S]
#pragma unroll
        for (int mt = 0; mt < 2; mt++)
#pragma unroll
            for (int half = 0; half < 2; half++) {
                int row = mbase + mt * 16 + r0 + half * 8;
                int bb2 = row >> 11;
                int sq = row & (SEQ - 1);
#pragma unroll
                for (int nt = 0; nt < 4; nt++) {
                    int jg = nbase + nt * 8 + c0;
                    outp[((size_t)bb2 * DMODEL + jg) * SEQ + sq] =
                        acc[mt][nt][half * 2 + 0] + bias[jg];
                    outp[((size_t)bb2 * DMODEL + jg + 1) * SEQ + sq] =
                        acc[mt][nt][half * 2 + 1] + bias[jg + 1];
                }
            }
    }
}

// ===================== tensor-core flash attention (2 CTAs/SM) =====================
// Br=128 (8 warps x m16), Bc=64. S = QhiKhi + QloKhi + QhiKlo (fp32 frags),
// softmax in fragments, P hi/lo in registers, O += PhiVhi + PloVhi + PhiVlo.
// smem (96KB/CTA -> 2 CTAs/SM): stage s at s*32768 (KH|KL|VH|VL 8K each),
// Q-hi persistent @65536 (16K), Q-lo persistent @81920 (16K).
// Q-hi fragments live in registers; Q-lo fragments re-ldmatrix'd per tile.
#define FL2_SMEM 98304
__global__ void __launch_bounds__(256, 2) k_flash2() {
    extern __shared__ char sm2[];
    uint32_t sb = smem_u32(sm2);
    int tid = threadIdx.x;
    int warp = tid >> 5, lane = tid & 31;
    int bh = blockIdx.y;
    int q0 = blockIdx.x * 128;

    const __nv_bfloat16* qh_g = g_qhi + ((size_t)bh * SEQ + q0) * HDIM;
    const __nv_bfloat16* ql_g = g_qlo + ((size_t)bh * SEQ + q0) * HDIM;
    const __nv_bfloat16* kh_g = g_khi + (size_t)bh * SEQ * HDIM;
    const __nv_bfloat16* kl_g = g_klo + (size_t)bh * SEQ * HDIM;
    const __nv_bfloat16* vh_g = g_vthi + (size_t)bh * HDIM * SEQ;
    const __nv_bfloat16* vl_g = g_vtlo + (size_t)bh * HDIM * SEQ;

#define FL_LOAD(s, kt) do {                                                     \
        uint32_t bs = sb + (uint32_t)(s) * 32768u;                              \
        int kb0 = (kt) * 64;                                                    \
        _Pragma("unroll") for (int it = 0; it < 2; it++) {                      \
            int c = it * 256 + tid;                                             \
            int r = c >> 3, col = c & 7;                                        \
            uint32_t off = (uint32_t)(r * 128 + col * 16);                      \
            off ^= (off >> 3) & 0x70;                                           \
            cpa16(bs + off, kh_g + (size_t)(kb0 + r) * HDIM + col * 8);         \
            cpa16(bs + 8192 + off, kl_g + (size_t)(kb0 + r) * HDIM + col * 8);  \
            cpa16(bs + 16384 + off, vh_g + (size_t)r * SEQ + kb0 + col * 8);    \
            cpa16(bs + 24576 + off, vl_g + (size_t)r * SEQ + kb0 + col * 8);    \
        }                                                                       \
    } while (0)

    // kick off first KV stage before Q staging (overlap)
    FL_LOAD(0, 0);
    CP_COMMIT;

    // ---- stage Q persistently: hi @65536, lo @81920
#pragma unroll
    for (int it = 0; it < 4; it++) {
        int c = it * 256 + tid;
        int r = c >> 3, col = c & 7;
        uint32_t off = (uint32_t)(r * 128 + col * 16);
        off ^= (off >> 3) & 0x70;
        *(uint4*)(sm2 + 65536 + off) = *(const uint4*)(qh_g + (size_t)r * HDIM + col * 8);
        *(uint4*)(sm2 + 81920 + off) = *(const uint4*)(ql_g + (size_t)r * HDIM + col * 8);
    }
    __syncthreads();

    // Q-hi fragments in registers (persistent); Q-lo re-loaded per tile
    int a_row = warp * 16 + (lane & 15);
    int a_kb = (lane >> 4) * 16;
    uint32_t qh[4][4];
#pragma unroll
    for (int t = 0; t < 4; t++) {
        uint32_t off = (uint32_t)(a_row * 128 + t * 32 + a_kb);
        off ^= (off >> 3) & 0x70;
        ldmx4(qh[t], sb + 65536u + off);
    }

    int b_row = (lane & 7) + ((lane >> 4) & 1) * 8;   // + pair*16
    int b_kb = ((lane >> 3) & 1) * 16;                // + t*32

    float oa[8][4];
#pragma unroll
    for (int j = 0; j < 8; j++)
#pragma unroll
        for (int e = 0; e < 4; e++) oa[j][e] = 0.0f;
    float m0 = -1e30f, m1 = -1e30f, l0 = 0.0f, l1 = 0.0f;

#pragma unroll 1
    for (int kt = 0; kt < SEQ / 64; kt++) {
        int s = kt & 1;
        if (kt + 1 < SEQ / 64) {
            FL_LOAD(s ^ 1, kt + 1);
            CP_COMMIT;
            CP_WAIT1;
        } else {
            CP_WAIT0;
        }
        __syncthreads();
        uint32_t kh_s = sb + (uint32_t)s * 32768u;
        uint32_t kl_s = kh_s + 8192u, vh_s = kh_s + 16384u, vl_s = kh_s + 24576u;

        // ---- S = Q K^T (3-term; same accumulation order as before)
        float sv[8][4];
#pragma unroll
        for (int j = 0; j < 8; j++)
#pragma unroll
            for (int e = 0; e < 4; e++) sv[j][e] = 0.0f;
#pragma unroll
        for (int t = 0; t < 4; t++) {
            uint32_t bf_[4][4];
            uint32_t offs[4];
#pragma unroll
            for (int p = 0; p < 4; p++) {
                uint32_t off = (uint32_t)((p * 16 + b_row) * 128 + t * 32 + b_kb);
                off ^= (off >> 3) & 0x70;
                offs[p] = off;
                ldmx4(bf_[p], kh_s + off);
            }
            // Q-lo fragment for this t (from persistent smem)
            uint32_t ql_t[4];
            {
                uint32_t qoff = (uint32_t)(a_row * 128 + t * 32 + a_kb);
                qoff ^= (qoff >> 3) & 0x70;
                ldmx4(ql_t, sb + 81920u + qoff);
            }
#pragma unroll
            for (int j = 0; j < 8; j++) mma16816(sv[j], qh[t], &bf_[j >> 1][(j & 1) * 2]);
#pragma unroll
            for (int j = 0; j < 8; j++) mma16816(sv[j], ql_t, &bf_[j >> 1][(j & 1) * 2]);
#pragma unroll
            for (int p = 0; p < 4; p++) ldmx4(bf_[p], kl_s + offs[p]);
#pragma unroll
            for (int j = 0; j < 8; j++) mma16816(sv[j], qh[t], &bf_[j >> 1][(j & 1) * 2]);
        }

        // ---- online softmax (rows r0 = d0,d1; r0+8 = d2,d3; reduce over quad)
        float mx0 = sv[0][0], mx1 = sv[0][2];
#pragma unroll
        for (int j = 0; j < 8; j++) {
            mx0 = fmaxf(mx0, fmaxf(sv[j][0], sv[j][1]));
            mx1 = fmaxf(mx1, fmaxf(sv[j][2], sv[j][3]));
        }
        mx0 = fmaxf(mx0, __shfl_xor_sync(0xffffffffu, mx0, 1));
        mx0 = fmaxf(mx0, __shfl_xor_sync(0xffffffffu, mx0, 2));
        mx1 = fmaxf(mx1, __shfl_xor_sync(0xffffffffu, mx1, 1));
        mx1 = fmaxf(mx1, __shfl_xor_sync(0xffffffffu, mx1, 2));
        float mn0 = fmaxf(m0, mx0), mn1 = fmaxf(m1, mx1);
        float al0 = __expf(m0 - mn0), al1 = __expf(m1 - mn1);
        m0 = mn0; m1 = mn1;
        float s0 = 0.0f, s1 = 0.0f;
#pragma unroll
        for (int j = 0; j < 8; j++) {
            sv[j][0] = __expf(sv[j][0] - mn0); s0 += sv[j][0];
            sv[j][1] = __expf(sv[j][1] - mn0); s0 += sv[j][1];
            sv[j][2] = __expf(sv[j][2] - mn1); s1 += sv[j][2];
            sv[j][3] = __expf(sv[j][3] - mn1); s1 += sv[j][3];
        }
        s0 += __shfl_xor_sync(0xffffffffu, s0, 1);
        s0 += __shfl_xor_sync(0xffffffffu, s0, 2);
        s1 += __shfl_xor_sync(0xffffffffu, s1, 1);
        s1 += __shfl_xor_sync(0xffffffffu, s1, 2);
        l0 = l0 * al0 + s0;
        l1 = l1 * al1 + s1;
#pragma unroll
        for (int j = 0; j < 8; j++) {
            oa[j][0] *= al0; oa[j][1] *= al0;
            oa[j][2] *= al1; oa[j][3] *= al1;
        }

        // ---- O += P V (3-term); P built from sv fragments in registers
#pragma unroll
        for (int t = 0; t < 4; t++) {
            uint32_t ph[4], pl[4];
            split2(sv[2 * t][0], sv[2 * t][1], ph[0], pl[0]);
            split2(sv[2 * t][2], sv[2 * t][3], ph[1], pl[1]);
            split2(sv[2 * t + 1][0], sv[2 * t + 1][1], ph[2], pl[2]);
            split2(sv[2 * t + 1][2], sv[2 * t + 1][3], ph[3], pl[3]);
            uint32_t vf[4][4];
            uint32_t offs[4];
#pragma unroll
            for (int p = 0; p < 4; p++) {
                uint32_t off = (uint32_t)((p * 16 + b_row) * 128 + t * 32 + b_kb);
                off ^= (off >> 3) & 0x70;
                offs[p] = off;
                ldmx4(vf[p], vh_s + off);
            }
#pragma unroll
            for (int j = 0; j < 8; j++) mma16816(oa[j], ph, &vf[j >> 1][(j & 1) * 2]);
#pragma unroll
            for (int j = 0; j < 8; j++) mma16816(oa[j], pl, &vf[j >> 1][(j & 1) * 2]);
#pragma unroll
            for (int p = 0; p < 4; p++) ldmx4(vf[p], vl_s + offs[p]);
#pragma unroll
            for (int j = 0; j < 8; j++) mma16816(oa[j], ph, &vf[j >> 1][(j & 1) * 2]);
        }
        __syncthreads();
    }

    // ---- epilogue: normalize, split, write to g_xhi/g_xlo in [b,s,d]
    float inv0 = 1.0f / l0, inv1 = 1.0f / l1;
    int bb = bh >> 4, h = bh & 15;
    int r0g = q0 + warp * 16 + (lane >> 2);
    int c0 = (lane & 3) * 2;
#pragma unroll
    for (int j = 0; j < 8; j++) {
        int hd = j * 8 + c0;
        uint32_t hi, lo;
        split2(oa[j][0] * inv0, oa[j][1] * inv0, hi, lo);
        size_t i0 = ((size_t)(bb * SEQ + r0g)) * DMODEL + h * HDIM + hd;
        *(uint32_t*)&g_xhi[i0] = hi;
        *(uint32_t*)&g_xlo[i0] = lo;
        split2(oa[j][2] * inv1, oa[j][3] * inv1, hi, lo);
        size_t i1 = i0 + (size_t)8 * DMODEL;
        *(uint32_t*)&g_xhi[i1] = hi;
        *(uint32_t*)&g_xlo[i1] = lo;
    }
}

// ===================== launch =====================
extern "C" void kernel_launch(void* const* d_in, const int* in_sizes, int n_in,
                              void* d_out, int out_size) {
    (void)in_sizes; (void)n_in; (void)out_size;
    const float* x  = (const float*)d_in[0];
    const float* Wq = (const float*)d_in[1];
    const float* bq = (const float*)d_in[2];
    const float* Wk = (const float*)d_in[3];
    const float* bk = (const float*)d_in[4];
    const float* Wv = (const float*)d_in[5];
    const float* bv = (const float*)d_in[6];
    const float* Wo = (const float*)d_in[7];
    const float* bo = (const float*)d_in[8];
    float* out = (float*)d_out;

    cudaFuncSetAttribute(k_mm, cudaFuncAttributeMaxDynamicSharedMemorySize, MM_SMEM);
    cudaFuncSetAttribute(k_flash2, cudaFuncAttributeMaxDynamicSharedMemorySize, FL2_SMEM);

    k_init_freq<<<1, 512>>>();
    k_pe_split<<<dim3(SEQ / 32, DMODEL / 32, BATCH), dim3(32, 8)>>>(x);
    k_split_w4<<<4096, 256>>>(Wq, Wk, Wv, Wo);

    // fused QKV: grid.z selects {Q, K, V}
    k_mm<<<dim3(DMODEL / 64, NTOK / 128, 3), 256, MM_SMEM>>>(bq, bk, bv, nullptr, 0);

    k_flash2<<<dim3(SEQ / 128, BATCH * NHEAD), 256, FL2_SMEM>>>();

    k_mm<<<dim3(DMODEL / 64, NTOK / 128, 1), 256, MM_SMEM>>>(bo, nullptr, nullptr, out, 1);
}